// round 1
// baseline (speedup 1.0000x reference)
#include <cuda_runtime.h>
#include <cuda_bf16.h>
#include <math.h>

// Problem dims (fixed by reference)
#define BATCH   16
#define SEQ     512
#define DM      1024
#define NHEADS  16
#define HD      64
#define DFF     4096
#define MTOK    (BATCH*SEQ)          // 8192 rows

// ---------------- scratch (device globals; no allocations allowed) ---------
__device__ float g_ln [MTOK * DM];        // ln1 out, reused for ln2 out
__device__ float g_qkv[MTOK * 3 * DM];    // qkv projections
__device__ float g_att[MTOK * DM];        // attention output (pre-proj)
__device__ float g_x1 [MTOK * DM];        // residual after attention
__device__ float g_ff [MTOK * DFF];       // ff1 activations

// ---------------------------------------------------------------------------
// LayerNorm: one block per row of 1024 floats.
// ---------------------------------------------------------------------------
__global__ void __launch_bounds__(256) ln_kernel(const float* __restrict__ x,
                                                 const float* __restrict__ g,
                                                 const float* __restrict__ b,
                                                 float* __restrict__ y)
{
    const int row = blockIdx.x;
    const int tid = threadIdx.x;
    const float4 v = *(const float4*)(x + (size_t)row * DM + tid * 4);

    float s1 = v.x + v.y + v.z + v.w;
    float s2 = v.x*v.x + v.y*v.y + v.z*v.z + v.w*v.w;

    // warp reduce
    #pragma unroll
    for (int o = 16; o > 0; o >>= 1) {
        s1 += __shfl_xor_sync(0xffffffffu, s1, o);
        s2 += __shfl_xor_sync(0xffffffffu, s2, o);
    }
    __shared__ float r1[8], r2[8];
    if ((tid & 31) == 0) { r1[tid >> 5] = s1; r2[tid >> 5] = s2; }
    __syncthreads();
    float t1 = r1[tid & 7], t2 = r2[tid & 7];
    #pragma unroll
    for (int o = 4; o > 0; o >>= 1) {
        t1 += __shfl_xor_sync(0xffffffffu, t1, o);
        t2 += __shfl_xor_sync(0xffffffffu, t2, o);
    }
    const float mu  = t1 * (1.0f / DM);
    const float var = t2 * (1.0f / DM) - mu * mu;
    const float inv = rsqrtf(var + 1e-5f);

    const float4 gg = *(const float4*)(g + tid * 4);
    const float4 bb = *(const float4*)(b + tid * 4);
    float4 o4;
    o4.x = (v.x - mu) * inv * gg.x + bb.x;
    o4.y = (v.y - mu) * inv * gg.y + bb.y;
    o4.z = (v.z - mu) * inv * gg.z + bb.z;
    o4.w = (v.w - mu) * inv * gg.w + bb.w;
    *(float4*)(y + (size_t)row * DM + tid * 4) = o4;
}

// ---------------------------------------------------------------------------
// GEMM: C[M,N] = A[M,K] @ B[N,K]^T  (+ epilogue).  Both operands K-contiguous.
// 128x128 block tile, BK=16, 8x8 per thread, 256 threads.
// EPI: 0 = none, 1 = +res, 2 = +bias,gelu, 3 = +bias,+res
// ---------------------------------------------------------------------------
template<int EPI>
__global__ void __launch_bounds__(256) gemm_nt(const float* __restrict__ A,
                                               const float* __restrict__ B,
                                               const float* __restrict__ bias,
                                               const float* __restrict__ res,
                                               float* __restrict__ C,
                                               int M, int N, int K)
{
    __shared__ float As[16][132];
    __shared__ float Bs[16][132];

    const int bm = blockIdx.y * 128;
    const int bn = blockIdx.x * 128;
    const int tid = threadIdx.x;

    const int lr = tid >> 1;            // 0..127 (tile row for loading)
    const int lc = (tid & 1) * 8;       // 0 or 8 (k-col base for loading)
    const float* Ag = A + (size_t)(bm + lr) * K + lc;
    const float* Bg = B + (size_t)(bn + lr) * K + lc;

    const int m0 = (tid >> 4) * 8;      // 0..120
    const int n0 = (tid & 15) * 8;

    float acc[8][8];
    #pragma unroll
    for (int i = 0; i < 8; i++)
        #pragma unroll
        for (int j = 0; j < 8; j++) acc[i][j] = 0.0f;

    for (int k0 = 0; k0 < K; k0 += 16) {
        const float4 a0 = *(const float4*)(Ag + k0);
        const float4 a1 = *(const float4*)(Ag + k0 + 4);
        const float4 b0 = *(const float4*)(Bg + k0);
        const float4 b1 = *(const float4*)(Bg + k0 + 4);
        __syncthreads();
        As[lc + 0][lr] = a0.x; As[lc + 1][lr] = a0.y;
        As[lc + 2][lr] = a0.z; As[lc + 3][lr] = a0.w;
        As[lc + 4][lr] = a1.x; As[lc + 5][lr] = a1.y;
        As[lc + 6][lr] = a1.z; As[lc + 7][lr] = a1.w;
        Bs[lc + 0][lr] = b0.x; Bs[lc + 1][lr] = b0.y;
        Bs[lc + 2][lr] = b0.z; Bs[lc + 3][lr] = b0.w;
        Bs[lc + 4][lr] = b1.x; Bs[lc + 5][lr] = b1.y;
        Bs[lc + 6][lr] = b1.z; Bs[lc + 7][lr] = b1.w;
        __syncthreads();

        #pragma unroll
        for (int kk = 0; kk < 16; kk++) {
            float a[8], b[8];
            *(float4*)&a[0] = *(const float4*)&As[kk][m0];
            *(float4*)&a[4] = *(const float4*)&As[kk][m0 + 4];
            *(float4*)&b[0] = *(const float4*)&Bs[kk][n0];
            *(float4*)&b[4] = *(const float4*)&Bs[kk][n0 + 4];
            #pragma unroll
            for (int i = 0; i < 8; i++)
                #pragma unroll
                for (int j = 0; j < 8; j++)
                    acc[i][j] = fmaf(a[i], b[j], acc[i][j]);
        }
    }

    // bias (per output column)
    float bv[8];
    if (EPI == 2 || EPI == 3) {
        *(float4*)&bv[0] = *(const float4*)(bias + bn + n0);
        *(float4*)&bv[4] = *(const float4*)(bias + bn + n0 + 4);
    }

    #pragma unroll
    for (int i = 0; i < 8; i++) {
        const size_t roff = (size_t)(bm + m0 + i) * N + bn + n0;
        float v[8];
        #pragma unroll
        for (int j = 0; j < 8; j++) v[j] = acc[i][j];
        if (EPI == 2 || EPI == 3) {
            #pragma unroll
            for (int j = 0; j < 8; j++) v[j] += bv[j];
        }
        if (EPI == 2) {  // exact GELU
            #pragma unroll
            for (int j = 0; j < 8; j++)
                v[j] = 0.5f * v[j] * (1.0f + erff(v[j] * 0.70710678118654752f));
        }
        if (EPI == 1 || EPI == 3) {
            float r[8];
            *(float4*)&r[0] = *(const float4*)(res + roff);
            *(float4*)&r[4] = *(const float4*)(res + roff + 4);
            #pragma unroll
            for (int j = 0; j < 8; j++) v[j] += r[j];
        }
        *(float4*)(C + roff)     = *(float4*)&v[0];
        *(float4*)(C + roff + 4) = *(float4*)&v[4];
    }
}

// ---------------------------------------------------------------------------
// Flash attention (fp32, causal). One block = one (b,h) and 64 query rows.
// Tiles: Br=Bc=64, hd=64. 256 threads, each owns a 4x4 sub-tile.
// qkv layout: [8192, 3072]; q at col h*64, k at 1024+h*64, v at 2048+h*64.
// ---------------------------------------------------------------------------
__global__ void __launch_bounds__(256) attn_kernel(const float* __restrict__ qkv,
                                                   float* __restrict__ out)
{
    extern __shared__ float sm[];
    float* Qt = sm;             // [64][64]  Qt[d*64 + r], pre-scaled
    float* Kt = sm + 4096;      // [64][64]  Kt[d*64 + c]
    float* Vs = sm + 8192;      // [64][64]  Vs[kc*64 + d]
    float* Pt = sm + 12288;     // [64][68]  Pt[kc*68 + r]

    const int bh = blockIdx.x;          // 0..255
    const int rb = blockIdx.y;          // 0..7 query row block
    const int b  = bh >> 4;
    const int h  = bh & 15;

    const float* Qg = qkv + (size_t)(b * SEQ) * (3 * DM) + h * HD;
    const float* Kg = Qg + DM;
    const float* Vg = Qg + 2 * DM;

    const int tid = threadIdx.x;
    const int tr = tid >> 4, tc = tid & 15;
    const int r0 = tr * 4, c0 = tc * 4;

    // ---- load Q tile (transposed, pre-scaled by 1/sqrt(hd)) ----
    {
        const int t = tid >> 2;                // 0..63
        const int dbase = (tid & 3) * 16;      // 0,16,32,48
        const float* src = Qg + (size_t)(rb * 64 + t) * (3 * DM) + dbase;
        #pragma unroll
        for (int j4 = 0; j4 < 4; j4++) {
            float4 v = *(const float4*)(src + j4 * 4);
            const int d = dbase + j4 * 4;
            Qt[(d + 0) * 64 + t] = v.x * 0.125f;
            Qt[(d + 1) * 64 + t] = v.y * 0.125f;
            Qt[(d + 2) * 64 + t] = v.z * 0.125f;
            Qt[(d + 3) * 64 + t] = v.w * 0.125f;
        }
    }

    float m[4], l[4], O[4][4];
    #pragma unroll
    for (int i = 0; i < 4; i++) {
        m[i] = -1e30f; l[i] = 0.0f;
        #pragma unroll
        for (int j = 0; j < 4; j++) O[i][j] = 0.0f;
    }

    for (int kb = 0; kb <= rb; kb++) {
        __syncthreads();   // prior iteration done with Kt/Vs/Pt
        // ---- load K (transposed) and V (row-major) tiles ----
        {
            const int t = tid >> 2;
            const int dbase = (tid & 3) * 16;
            const float* ks = Kg + (size_t)(kb * 64 + t) * (3 * DM) + dbase;
            const float* vs = Vg + (size_t)(kb * 64 + t) * (3 * DM) + dbase;
            #pragma unroll
            for (int j4 = 0; j4 < 4; j4++) {
                float4 kv = *(const float4*)(ks + j4 * 4);
                const int d = dbase + j4 * 4;
                Kt[(d + 0) * 64 + t] = kv.x;
                Kt[(d + 1) * 64 + t] = kv.y;
                Kt[(d + 2) * 64 + t] = kv.z;
                Kt[(d + 3) * 64 + t] = kv.w;
                *(float4*)(Vs + t * 64 + d) = *(const float4*)(vs + j4 * 4);
            }
        }
        __syncthreads();

        // ---- S = (Q*scale) @ K^T  (4x4 per thread) ----
        float s[4][4];
        #pragma unroll
        for (int i = 0; i < 4; i++)
            #pragma unroll
            for (int j = 0; j < 4; j++) s[i][j] = 0.0f;
        #pragma unroll 16
        for (int d = 0; d < 64; d++) {
            float4 qv = *(const float4*)(Qt + d * 64 + r0);
            float4 kv = *(const float4*)(Kt + d * 64 + c0);
            const float qa[4] = {qv.x, qv.y, qv.z, qv.w};
            const float ka[4] = {kv.x, kv.y, kv.z, kv.w};
            #pragma unroll
            for (int i = 0; i < 4; i++)
                #pragma unroll
                for (int j = 0; j < 4; j++)
                    s[i][j] = fmaf(qa[i], ka[j], s[i][j]);
        }

        // ---- causal mask on diagonal block (matches ref: -10000 after scale)
        if (kb == rb) {
            #pragma unroll
            for (int i = 0; i < 4; i++)
                #pragma unroll
                for (int j = 0; j < 4; j++)
                    if (c0 + j > r0 + i) s[i][j] = -10000.0f;
        }

        // ---- online softmax ----
        #pragma unroll
        for (int i = 0; i < 4; i++) {
            float rm = fmaxf(fmaxf(s[i][0], s[i][1]), fmaxf(s[i][2], s[i][3]));
            #pragma unroll
            for (int o = 8; o > 0; o >>= 1)
                rm = fmaxf(rm, __shfl_xor_sync(0xffffffffu, rm, o));
            const float mn = fmaxf(m[i], rm);
            const float alpha = __expf(m[i] - mn);
            float rs = 0.0f;
            #pragma unroll
            for (int j = 0; j < 4; j++) {
                s[i][j] = __expf(s[i][j] - mn);
                rs += s[i][j];
            }
            #pragma unroll
            for (int o = 8; o > 0; o >>= 1)
                rs += __shfl_xor_sync(0xffffffffu, rs, o);
            l[i] = l[i] * alpha + rs;
            m[i] = mn;
            #pragma unroll
            for (int j = 0; j < 4; j++) O[i][j] *= alpha;
        }

        // ---- write P transposed, then O += P @ V ----
        #pragma unroll
        for (int j = 0; j < 4; j++)
            #pragma unroll
            for (int i = 0; i < 4; i++)
                Pt[(c0 + j) * 68 + r0 + i] = s[i][j];
        __syncthreads();

        #pragma unroll 16
        for (int kc = 0; kc < 64; kc++) {
            float4 pv = *(const float4*)(Pt + kc * 68 + r0);
            float4 vv = *(const float4*)(Vs + kc * 64 + c0);
            const float pa[4] = {pv.x, pv.y, pv.z, pv.w};
            const float va[4] = {vv.x, vv.y, vv.z, vv.w};
            #pragma unroll
            for (int i = 0; i < 4; i++)
                #pragma unroll
                for (int j = 0; j < 4; j++)
                    O[i][j] = fmaf(pa[i], va[j], O[i][j]);
        }
    }

    // ---- normalize + store: out[b*512 + rb*64 + r, h*64 + c] ----
    #pragma unroll
    for (int i = 0; i < 4; i++) {
        const float inv = 1.0f / l[i];
        float4 o4;
        o4.x = O[i][0] * inv; o4.y = O[i][1] * inv;
        o4.z = O[i][2] * inv; o4.w = O[i][3] * inv;
        const size_t row = (size_t)(b * SEQ + rb * 64 + r0 + i);
        *(float4*)(out + row * DM + h * HD + c0) = o4;
    }
}

// ---------------------------------------------------------------------------
extern "C" void kernel_launch(void* const* d_in, const int* in_sizes, int n_in,
                              void* d_out, int out_size)
{
    const float* x      = (const float*)d_in[0];
    const float* w_qkv  = (const float*)d_in[1];
    const float* w_proj = (const float*)d_in[2];
    const float* w_ff1  = (const float*)d_in[3];
    const float* b_ff1  = (const float*)d_in[4];
    const float* w_ff2  = (const float*)d_in[5];
    const float* b_ff2  = (const float*)d_in[6];
    const float* ln1_g  = (const float*)d_in[7];
    const float* ln1_b  = (const float*)d_in[8];
    const float* ln2_g  = (const float*)d_in[9];
    const float* ln2_b  = (const float*)d_in[10];
    float* out = (float*)d_out;

    float *p_ln, *p_qkv, *p_att, *p_x1, *p_ff;
    cudaGetSymbolAddress((void**)&p_ln,  g_ln);
    cudaGetSymbolAddress((void**)&p_qkv, g_qkv);
    cudaGetSymbolAddress((void**)&p_att, g_att);
    cudaGetSymbolAddress((void**)&p_x1,  g_x1);
    cudaGetSymbolAddress((void**)&p_ff,  g_ff);

    const int ATTN_SMEM = (4096 * 3 + 64 * 68) * 4;   // 66560 B
    cudaFuncSetAttribute(attn_kernel,
                         cudaFuncAttributeMaxDynamicSharedMemorySize, ATTN_SMEM);

    // 1. LN1
    ln_kernel<<<MTOK, 256>>>(x, ln1_g, ln1_b, p_ln);
    // 2. QKV projection: [8192,3072]
    gemm_nt<0><<<dim3(3 * DM / 128, MTOK / 128), 256>>>(
        p_ln, w_qkv, nullptr, nullptr, p_qkv, MTOK, 3 * DM, DM);
    // 3. causal flash attention
    attn_kernel<<<dim3(BATCH * NHEADS, SEQ / 64), 256, ATTN_SMEM>>>(p_qkv, p_att);
    // 4. out projection + residual: x1 = x + att @ Wp^T
    gemm_nt<1><<<dim3(DM / 128, MTOK / 128), 256>>>(
        p_att, w_proj, nullptr, x, p_x1, MTOK, DM, DM);
    // 5. LN2 (reuse g_ln)
    ln_kernel<<<MTOK, 256>>>(p_x1, ln2_g, ln2_b, p_ln);
    // 6. FF1 + bias + exact GELU: [8192,4096]
    gemm_nt<2><<<dim3(DFF / 128, MTOK / 128), 256>>>(
        p_ln, w_ff1, b_ff1, nullptr, p_ff, MTOK, DFF, DM);
    // 7. FF2 + bias + residual -> out
    gemm_nt<3><<<dim3(DM / 128, MTOK / 128), 256>>>(
        p_ff, w_ff2, b_ff2, p_x1, out, MTOK, DM, DFF);
}

// round 3
// speedup vs baseline: 1.9841x; 1.9841x over previous
#include <cuda_runtime.h>
#include <cuda_bf16.h>
#include <math.h>
#include <cstdint>

// Problem dims (fixed by reference)
#define BATCH   16
#define SEQ     512
#define DM      1024
#define NHEADS  16
#define HD      64
#define DFF     4096
#define MTOK    (BATCH*SEQ)          // 8192 rows

// ---------------- scratch (device globals; no allocations allowed) ---------
__device__ float g_ln [MTOK * DM];
__device__ float g_qkv[MTOK * 3 * DM];
__device__ float g_att[MTOK * DM];
__device__ float g_x1 [MTOK * DM];
__device__ float g_ff [MTOK * DFF];

#define SMEM_SWIZZLE_128B(byte_offset) \
    ((byte_offset) ^ (((byte_offset) >> 3) & 0x70))

__device__ __forceinline__ uint32_t smem_to_u32(const void* smem_ptr) {
    uint32_t addr;
    asm("{ .reg .u64 tmp; cvta.to.shared.u64 tmp, %1; cvt.u32.u64 %0, tmp; }"
        : "=r"(addr) : "l"(smem_ptr));
    return addr;
}

__device__ __forceinline__ void ldmatrix_x4(uint32_t& r0, uint32_t& r1,
                                            uint32_t& r2, uint32_t& r3,
                                            uint32_t addr) {
    asm volatile("ldmatrix.sync.aligned.m8n8.x4.shared.b16 {%0,%1,%2,%3}, [%4];"
                 : "=r"(r0), "=r"(r1), "=r"(r2), "=r"(r3) : "r"(addr));
}

__device__ __forceinline__ void mma_bf16(float* c, const uint32_t* a,
                                         const uint32_t* b) {
    asm volatile(
        "mma.sync.aligned.m16n8k16.row.col.f32.bf16.bf16.f32 "
        "{%0,%1,%2,%3}, {%4,%5,%6,%7}, {%8,%9}, {%0,%1,%2,%3};"
        : "+f"(c[0]), "+f"(c[1]), "+f"(c[2]), "+f"(c[3])
        : "r"(a[0]), "r"(a[1]), "r"(a[2]), "r"(a[3]), "r"(b[0]), "r"(b[1]));
}

// split one float4 into hi/lo bf16 quads packed as 2x u32 each
__device__ __forceinline__ void split4(const float4 v, uint32_t* hi, uint32_t* lo) {
    __nv_bfloat16 hx = __float2bfloat16(v.x);
    __nv_bfloat16 hy = __float2bfloat16(v.y);
    __nv_bfloat16 hz = __float2bfloat16(v.z);
    __nv_bfloat16 hw = __float2bfloat16(v.w);
    __nv_bfloat16 lx = __float2bfloat16(v.x - __bfloat162float(hx));
    __nv_bfloat16 ly = __float2bfloat16(v.y - __bfloat162float(hy));
    __nv_bfloat16 lz = __float2bfloat16(v.z - __bfloat162float(hz));
    __nv_bfloat16 lw = __float2bfloat16(v.w - __bfloat162float(hw));
    __nv_bfloat162 h0; h0.x = hx; h0.y = hy;
    __nv_bfloat162 h1; h1.x = hz; h1.y = hw;
    __nv_bfloat162 l0; l0.x = lx; l0.y = ly;
    __nv_bfloat162 l1; l1.x = lz; l1.y = lw;
    hi[0] = *(uint32_t*)&h0; hi[1] = *(uint32_t*)&h1;
    lo[0] = *(uint32_t*)&l0; lo[1] = *(uint32_t*)&l1;
}

// ---------------------------------------------------------------------------
// LayerNorm: one block per row of 1024 floats.
// ---------------------------------------------------------------------------
__global__ void __launch_bounds__(256) ln_kernel(const float* __restrict__ x,
                                                 const float* __restrict__ g,
                                                 const float* __restrict__ b,
                                                 float* __restrict__ y)
{
    const int row = blockIdx.x;
    const int tid = threadIdx.x;
    const float4 v = *(const float4*)(x + (size_t)row * DM + tid * 4);

    float s1 = v.x + v.y + v.z + v.w;
    float s2 = v.x*v.x + v.y*v.y + v.z*v.z + v.w*v.w;

    #pragma unroll
    for (int o = 16; o > 0; o >>= 1) {
        s1 += __shfl_xor_sync(0xffffffffu, s1, o);
        s2 += __shfl_xor_sync(0xffffffffu, s2, o);
    }
    __shared__ float r1[8], r2[8];
    if ((tid & 31) == 0) { r1[tid >> 5] = s1; r2[tid >> 5] = s2; }
    __syncthreads();
    float t1 = r1[tid & 7], t2 = r2[tid & 7];
    #pragma unroll
    for (int o = 4; o > 0; o >>= 1) {
        t1 += __shfl_xor_sync(0xffffffffu, t1, o);
        t2 += __shfl_xor_sync(0xffffffffu, t2, o);
    }
    const float mu  = t1 * (1.0f / DM);
    const float var = t2 * (1.0f / DM) - mu * mu;
    const float inv = rsqrtf(var + 1e-5f);

    const float4 gg = *(const float4*)(g + tid * 4);
    const float4 bb = *(const float4*)(b + tid * 4);
    float4 o4;
    o4.x = (v.x - mu) * inv * gg.x + bb.x;
    o4.y = (v.y - mu) * inv * gg.y + bb.y;
    o4.z = (v.z - mu) * inv * gg.z + bb.z;
    o4.w = (v.w - mu) * inv * gg.w + bb.w;
    *(float4*)(y + (size_t)row * DM + tid * 4) = o4;
}

// ---------------------------------------------------------------------------
// Tensor-core GEMM via legacy mma.sync (bf16, 3x split for fp32 precision).
// C[M,N] = A[M,K] @ B[N,K]^T (+epilogue). Both operands K-contiguous.
// 128x128 CTA tile, BK=32 fp32, 256 threads = 8 warps (2m x 4n), warp: 64x32.
// smem rows: 128 bytes = [hi: 32 bf16 | lo: 32 bf16], XOR-swizzled.
// EPI: 0 none, 1 +res, 2 +bias,gelu, 3 +bias,+res
// ---------------------------------------------------------------------------
template<int EPI>
__global__ void __launch_bounds__(256) gemm_mma(const float* __restrict__ A,
                                                const float* __restrict__ B,
                                                const float* __restrict__ bias,
                                                const float* __restrict__ res,
                                                float* __restrict__ C,
                                                int M, int N, int K)
{
    __shared__ __align__(1024) char As[128 * 128];   // 16KB
    __shared__ __align__(1024) char Bs[128 * 128];   // 16KB

    const int tid  = threadIdx.x;
    const int wid  = tid >> 5;
    const int lane = tid & 31;
    const int bm = blockIdx.y * 128;
    const int bn = blockIdx.x * 128;

    const int warpM = (wid >> 2) * 64;     // 0 or 64
    const int warpN = (wid & 3) * 32;      // 0,32,64,96

    const uint32_t AsU = smem_to_u32(As);
    const uint32_t BsU = smem_to_u32(Bs);

    // ldmatrix per-thread address components
    const int aRow = ((lane >> 3) & 1) * 8 + (lane & 7);   // + mt*16 + warpM
    const int aCol = (lane >> 4) * 16;                     // byte offset within k-chunk
    const int bRow = (lane >> 4) * 8 + (lane & 7);         // + p*16 + warpN
    const int bCol = ((lane >> 3) & 1) * 16;

    const int g   = lane >> 2;
    const int tig = lane & 3;

    float acc[4][4][4];
    #pragma unroll
    for (int mt = 0; mt < 4; mt++)
        #pragma unroll
        for (int nt = 0; nt < 4; nt++)
            #pragma unroll
            for (int q = 0; q < 4; q++) acc[mt][nt][q] = 0.0f;

    const float* Ag = A + (size_t)bm * K;
    const float* Bg = B + (size_t)bn * K;

    const int NIT = K >> 5;

    float4 pa[4], pb[4];
    #pragma unroll
    for (int i = 0; i < 4; i++) {
        const int f = tid + i * 256;       // 0..1023 float4 index
        const int row = f >> 3, c4 = f & 7;
        pa[i] = *(const float4*)(Ag + (size_t)row * K + c4 * 4);
        pb[i] = *(const float4*)(Bg + (size_t)row * K + c4 * 4);
    }

    for (int it = 0; it < NIT; ++it) {
        if (it > 0) __syncthreads();       // all warps done reading prev tile
        // ---- split + store to smem (hi at col byte 2k, lo at 64+2k) ----
        #pragma unroll
        for (int i = 0; i < 4; i++) {
            const int f = tid + i * 256;
            const int row = f >> 3, c4 = f & 7;
            uint32_t hi[2], lo[2];
            split4(pa[i], hi, lo);
            const uint32_t offh = SMEM_SWIZZLE_128B((uint32_t)(row * 128 + c4 * 8));
            const uint32_t offl = SMEM_SWIZZLE_128B((uint32_t)(row * 128 + 64 + c4 * 8));
            *(uint2*)(As + offh) = make_uint2(hi[0], hi[1]);
            *(uint2*)(As + offl) = make_uint2(lo[0], lo[1]);
            split4(pb[i], hi, lo);
            *(uint2*)(Bs + offh) = make_uint2(hi[0], hi[1]);
            *(uint2*)(Bs + offl) = make_uint2(lo[0], lo[1]);
        }
        __syncthreads();

        // ---- prefetch next K-tile (in flight during MMA) ----
        if (it + 1 < NIT) {
            const int koff = (it + 1) * 32;
            #pragma unroll
            for (int i = 0; i < 4; i++) {
                const int f = tid + i * 256;
                const int row = f >> 3, c4 = f & 7;
                pa[i] = *(const float4*)(Ag + (size_t)row * K + koff + c4 * 4);
                pb[i] = *(const float4*)(Bg + (size_t)row * K + koff + c4 * 4);
            }
        }

        // ---- 2 k16 steps, 3 passes each ----
        #pragma unroll
        for (int s = 0; s < 2; s++) {
            const int kbH = s * 32;        // hi bytes
            const int kbL = 64 + s * 32;   // lo bytes

            uint32_t ahi[4][4], alo[4][4], bhi[2][4], blo[2][4];
            #pragma unroll
            for (int mt = 0; mt < 4; mt++) {
                const int r = warpM + mt * 16 + aRow;
                ldmatrix_x4(ahi[mt][0], ahi[mt][1], ahi[mt][2], ahi[mt][3],
                    AsU + SMEM_SWIZZLE_128B((uint32_t)(r * 128 + kbH + aCol)));
                ldmatrix_x4(alo[mt][0], alo[mt][1], alo[mt][2], alo[mt][3],
                    AsU + SMEM_SWIZZLE_128B((uint32_t)(r * 128 + kbL + aCol)));
            }
            #pragma unroll
            for (int p = 0; p < 2; p++) {
                const int r = warpN + p * 16 + bRow;
                ldmatrix_x4(bhi[p][0], bhi[p][1], bhi[p][2], bhi[p][3],
                    BsU + SMEM_SWIZZLE_128B((uint32_t)(r * 128 + kbH + bCol)));
                ldmatrix_x4(blo[p][0], blo[p][1], blo[p][2], blo[p][3],
                    BsU + SMEM_SWIZZLE_128B((uint32_t)(r * 128 + kbL + bCol)));
            }

            #pragma unroll
            for (int mt = 0; mt < 4; mt++)
                #pragma unroll
                for (int nt = 0; nt < 4; nt++) {
                    const uint32_t* bh = &bhi[nt >> 1][(nt & 1) * 2];
                    const uint32_t* bl = &blo[nt >> 1][(nt & 1) * 2];
                    mma_bf16(acc[mt][nt], ahi[mt], bh);   // hi*hi
                    mma_bf16(acc[mt][nt], alo[mt], bh);   // lo*hi
                    mma_bf16(acc[mt][nt], ahi[mt], bl);   // hi*lo
                }
        }
    }

    // ---- epilogue ----
    #pragma unroll
    for (int mt = 0; mt < 4; mt++) {
        #pragma unroll
        for (int nt = 0; nt < 4; nt++) {
            const int col  = bn + warpN + nt * 8 + tig * 2;
            float v[4];
            #pragma unroll
            for (int q = 0; q < 4; q++) v[q] = acc[mt][nt][q];

            if (EPI == 2 || EPI == 3) {
                const float2 bv = *(const float2*)(bias + col);
                v[0] += bv.x; v[1] += bv.y; v[2] += bv.x; v[3] += bv.y;
            }
            if (EPI == 2) {
                #pragma unroll
                for (int q = 0; q < 4; q++)
                    v[q] = 0.5f * v[q] * (1.0f + erff(v[q] * 0.70710678118654752f));
            }
            const int row0 = bm + warpM + mt * 16 + g;
            const int row1 = row0 + 8;
            const size_t o0 = (size_t)row0 * N + col;
            const size_t o1 = (size_t)row1 * N + col;
            if (EPI == 1 || EPI == 3) {
                const float2 r0 = *(const float2*)(res + o0);
                const float2 r1 = *(const float2*)(res + o1);
                v[0] += r0.x; v[1] += r0.y; v[2] += r1.x; v[3] += r1.y;
            }
            *(float2*)(C + o0) = make_float2(v[0], v[1]);
            *(float2*)(C + o1) = make_float2(v[2], v[3]);
        }
    }
}

// ---------------------------------------------------------------------------
// Flash attention (fp32, causal). One block = one (b,h) and 64 query rows.
// ---------------------------------------------------------------------------
__global__ void __launch_bounds__(256) attn_kernel(const float* __restrict__ qkv,
                                                   float* __restrict__ out)
{
    extern __shared__ float sm[];
    float* Qt = sm;             // [64][64]  Qt[d*64 + r], pre-scaled
    float* Kt = sm + 4096;      // [64][64]  Kt[d*64 + c]
    float* Vs = sm + 8192;      // [64][64]  Vs[kc*64 + d]
    float* Pt = sm + 12288;     // [64][68]  Pt[kc*68 + r]

    const int bh = blockIdx.x;
    const int rb = blockIdx.y;
    const int b  = bh >> 4;
    const int h  = bh & 15;

    const float* Qg = qkv + (size_t)(b * SEQ) * (3 * DM) + h * HD;
    const float* Kg = Qg + DM;
    const float* Vg = Qg + 2 * DM;

    const int tid = threadIdx.x;
    const int tr = tid >> 4, tc = tid & 15;
    const int r0 = tr * 4, c0 = tc * 4;

    {
        const int t = tid >> 2;
        const int dbase = (tid & 3) * 16;
        const float* src = Qg + (size_t)(rb * 64 + t) * (3 * DM) + dbase;
        #pragma unroll
        for (int j4 = 0; j4 < 4; j4++) {
            float4 v = *(const float4*)(src + j4 * 4);
            const int d = dbase + j4 * 4;
            Qt[(d + 0) * 64 + t] = v.x * 0.125f;
            Qt[(d + 1) * 64 + t] = v.y * 0.125f;
            Qt[(d + 2) * 64 + t] = v.z * 0.125f;
            Qt[(d + 3) * 64 + t] = v.w * 0.125f;
        }
    }

    float m[4], l[4], O[4][4];
    #pragma unroll
    for (int i = 0; i < 4; i++) {
        m[i] = -1e30f; l[i] = 0.0f;
        #pragma unroll
        for (int j = 0; j < 4; j++) O[i][j] = 0.0f;
    }

    for (int kb = 0; kb <= rb; kb++) {
        __syncthreads();
        {
            const int t = tid >> 2;
            const int dbase = (tid & 3) * 16;
            const float* ks = Kg + (size_t)(kb * 64 + t) * (3 * DM) + dbase;
            const float* vs = Vg + (size_t)(kb * 64 + t) * (3 * DM) + dbase;
            #pragma unroll
            for (int j4 = 0; j4 < 4; j4++) {
                float4 kv = *(const float4*)(ks + j4 * 4);
                const int d = dbase + j4 * 4;
                Kt[(d + 0) * 64 + t] = kv.x;
                Kt[(d + 1) * 64 + t] = kv.y;
                Kt[(d + 2) * 64 + t] = kv.z;
                Kt[(d + 3) * 64 + t] = kv.w;
                *(float4*)(Vs + t * 64 + d) = *(const float4*)(vs + j4 * 4);
            }
        }
        __syncthreads();

        float s[4][4];
        #pragma unroll
        for (int i = 0; i < 4; i++)
            #pragma unroll
            for (int j = 0; j < 4; j++) s[i][j] = 0.0f;
        #pragma unroll 16
        for (int d = 0; d < 64; d++) {
            float4 qv = *(const float4*)(Qt + d * 64 + r0);
            float4 kv = *(const float4*)(Kt + d * 64 + c0);
            const float qa[4] = {qv.x, qv.y, qv.z, qv.w};
            const float ka[4] = {kv.x, kv.y, kv.z, kv.w};
            #pragma unroll
            for (int i = 0; i < 4; i++)
                #pragma unroll
                for (int j = 0; j < 4; j++)
                    s[i][j] = fmaf(qa[i], ka[j], s[i][j]);
        }

        if (kb == rb) {
            #pragma unroll
            for (int i = 0; i < 4; i++)
                #pragma unroll
                for (int j = 0; j < 4; j++)
                    if (c0 + j > r0 + i) s[i][j] = -10000.0f;
        }

        #pragma unroll
        for (int i = 0; i < 4; i++) {
            float rm = fmaxf(fmaxf(s[i][0], s[i][1]), fmaxf(s[i][2], s[i][3]));
            #pragma unroll
            for (int o = 8; o > 0; o >>= 1)
                rm = fmaxf(rm, __shfl_xor_sync(0xffffffffu, rm, o));
            const float mn = fmaxf(m[i], rm);
            const float alpha = __expf(m[i] - mn);
            float rs = 0.0f;
            #pragma unroll
            for (int j = 0; j < 4; j++) {
                s[i][j] = __expf(s[i][j] - mn);
                rs += s[i][j];
            }
            #pragma unroll
            for (int o = 8; o > 0; o >>= 1)
                rs += __shfl_xor_sync(0xffffffffu, rs, o);
            l[i] = l[i] * alpha + rs;
            m[i] = mn;
            #pragma unroll
            for (int j = 0; j < 4; j++) O[i][j] *= alpha;
        }

        #pragma unroll
        for (int j = 0; j < 4; j++)
            #pragma unroll
            for (int i = 0; i < 4; i++)
                Pt[(c0 + j) * 68 + r0 + i] = s[i][j];
        __syncthreads();

        #pragma unroll 16
        for (int kc = 0; kc < 64; kc++) {
            float4 pv = *(const float4*)(Pt + kc * 68 + r0);
            float4 vv = *(const float4*)(Vs + kc * 64 + c0);
            const float pa[4] = {pv.x, pv.y, pv.z, pv.w};
            const float va[4] = {vv.x, vv.y, vv.z, vv.w};
            #pragma unroll
            for (int i = 0; i < 4; i++)
                #pragma unroll
                for (int j = 0; j < 4; j++)
                    O[i][j] = fmaf(pa[i], va[j], O[i][j]);
        }
    }

    #pragma unroll
    for (int i = 0; i < 4; i++) {
        const float inv = 1.0f / l[i];
        float4 o4;
        o4.x = O[i][0] * inv; o4.y = O[i][1] * inv;
        o4.z = O[i][2] * inv; o4.w = O[i][3] * inv;
        const size_t row = (size_t)(b * SEQ + rb * 64 + r0 + i);
        *(float4*)(out + row * DM + h * HD + c0) = o4;
    }
}

// ---------------------------------------------------------------------------
extern "C" void kernel_launch(void* const* d_in, const int* in_sizes, int n_in,
                              void* d_out, int out_size)
{
    const float* x      = (const float*)d_in[0];
    const float* w_qkv  = (const float*)d_in[1];
    const float* w_proj = (const float*)d_in[2];
    const float* w_ff1  = (const float*)d_in[3];
    const float* b_ff1  = (const float*)d_in[4];
    const float* w_ff2  = (const float*)d_in[5];
    const float* b_ff2  = (const float*)d_in[6];
    const float* ln1_g  = (const float*)d_in[7];
    const float* ln1_b  = (const float*)d_in[8];
    const float* ln2_g  = (const float*)d_in[9];
    const float* ln2_b  = (const float*)d_in[10];
    float* out = (float*)d_out;

    float *p_ln, *p_qkv, *p_att, *p_x1, *p_ff;
    cudaGetSymbolAddress((void**)&p_ln,  g_ln);
    cudaGetSymbolAddress((void**)&p_qkv, g_qkv);
    cudaGetSymbolAddress((void**)&p_att, g_att);
    cudaGetSymbolAddress((void**)&p_x1,  g_x1);
    cudaGetSymbolAddress((void**)&p_ff,  g_ff);

    const int ATTN_SMEM = (4096 * 3 + 64 * 68) * 4;   // 66560 B
    cudaFuncSetAttribute(attn_kernel,
                         cudaFuncAttributeMaxDynamicSharedMemorySize, ATTN_SMEM);

    // 1. LN1
    ln_kernel<<<MTOK, 256>>>(x, ln1_g, ln1_b, p_ln);
    // 2. QKV projection: [8192,3072]
    gemm_mma<0><<<dim3(3 * DM / 128, MTOK / 128), 256>>>(
        p_ln, w_qkv, nullptr, nullptr, p_qkv, MTOK, 3 * DM, DM);
    // 3. causal flash attention
    attn_kernel<<<dim3(BATCH * NHEADS, SEQ / 64), 256, ATTN_SMEM>>>(p_qkv, p_att);
    // 4. out projection + residual: x1 = x + att @ Wp^T
    gemm_mma<1><<<dim3(DM / 128, MTOK / 128), 256>>>(
        p_att, w_proj, nullptr, x, p_x1, MTOK, DM, DM);
    // 5. LN2 (reuse g_ln)
    ln_kernel<<<MTOK, 256>>>(p_x1, ln2_g, ln2_b, p_ln);
    // 6. FF1 + bias + exact GELU: [8192,4096]
    gemm_mma<2><<<dim3(DFF / 128, MTOK / 128), 256>>>(
        p_ln, w_ff1, b_ff1, nullptr, p_ff, MTOK, DFF, DM);
    // 7. FF2 + bias + residual -> out
    gemm_mma<3><<<dim3(DM / 128, MTOK / 128), 256>>>(
        p_ff, w_ff2, b_ff2, p_x1, out, MTOK, DM, DFF);
}

// round 5
// speedup vs baseline: 2.5878x; 1.3043x over previous
#include <cuda_runtime.h>
#include <cuda_bf16.h>
#include <math.h>
#include <cstdint>

// Problem dims (fixed by reference)
#define BATCH   16
#define SEQ     512
#define DM      1024
#define NHEADS  16
#define HD      64
#define DFF     4096
#define MTOK    (BATCH*SEQ)          // 8192 rows

// ---------------- scratch (device globals; no allocations allowed) ---------
// "split format": per logical row of K fp32, bytes laid out as K/32 blocks of
// 128B: [32 hi bf16 | 32 lo bf16]. Element (r,k): base + r*K*4 + (k>>5)*128 +
// (k&31)*2 (hi), +64 (lo). Directly cp.async-able into swizzled smem.
__device__ uint8_t g_lns [MTOK * DM * 4];        // ln1/ln2 out (split)
__device__ float   g_qkv [MTOK * 3 * DM];        // qkv projections (fp32)
__device__ uint8_t g_atts[MTOK * DM * 4];        // attention out (split)
__device__ float   g_x1  [MTOK * DM];            // residual after attention
__device__ uint8_t g_ffs [MTOK * DFF * 4];       // ff1 activations (split)
__device__ uint8_t g_wqkv[3 * DM * DM * 4];      // split weights
__device__ uint8_t g_wprj[DM * DM * 4];
__device__ uint8_t g_wff1[DFF * DM * 4];
__device__ uint8_t g_wff2[DM * DFF * 4];

#define SMEM_SWIZZLE_128B(byte_offset) \
    ((byte_offset) ^ (((byte_offset) >> 3) & 0x70))

__device__ __forceinline__ uint32_t smem_to_u32(const void* smem_ptr) {
    uint32_t addr;
    asm("{ .reg .u64 tmp; cvta.to.shared.u64 tmp, %1; cvt.u32.u64 %0, tmp; }"
        : "=r"(addr) : "l"(smem_ptr));
    return addr;
}

__device__ __forceinline__ void cp_async16(uint32_t dst, const void* src) {
    asm volatile("cp.async.ca.shared.global [%0], [%1], 16;"
                 :: "r"(dst), "l"(src));
}
#define CP_COMMIT() asm volatile("cp.async.commit_group;" ::: "memory")
#define CP_WAIT(n)  asm volatile("cp.async.wait_group %0;" :: "n"(n) : "memory")

__device__ __forceinline__ void ldmatrix_x4(uint32_t& r0, uint32_t& r1,
                                            uint32_t& r2, uint32_t& r3,
                                            uint32_t addr) {
    asm volatile("ldmatrix.sync.aligned.m8n8.x4.shared.b16 {%0,%1,%2,%3}, [%4];"
                 : "=r"(r0), "=r"(r1), "=r"(r2), "=r"(r3) : "r"(addr));
}

__device__ __forceinline__ void mma_bf16(float* c, const uint32_t* a,
                                         const uint32_t* b) {
    asm volatile(
        "mma.sync.aligned.m16n8k16.row.col.f32.bf16.bf16.f32 "
        "{%0,%1,%2,%3}, {%4,%5,%6,%7}, {%8,%9}, {%0,%1,%2,%3};"
        : "+f"(c[0]), "+f"(c[1]), "+f"(c[2]), "+f"(c[3])
        : "r"(a[0]), "r"(a[1]), "r"(a[2]), "r"(a[3]), "r"(b[0]), "r"(b[1]));
}

// pack 4 floats into hi uint2 (4 bf16) and lo uint2 (residual bf16)
__device__ __forceinline__ void split4_pack(const float4 v, uint2& hi, uint2& lo) {
    __nv_bfloat16 hx = __float2bfloat16(v.x);
    __nv_bfloat16 hy = __float2bfloat16(v.y);
    __nv_bfloat16 hz = __float2bfloat16(v.z);
    __nv_bfloat16 hw = __float2bfloat16(v.w);
    __nv_bfloat16 lx = __float2bfloat16(v.x - __bfloat162float(hx));
    __nv_bfloat16 ly = __float2bfloat16(v.y - __bfloat162float(hy));
    __nv_bfloat16 lz = __float2bfloat16(v.z - __bfloat162float(hz));
    __nv_bfloat16 lw = __float2bfloat16(v.w - __bfloat162float(hw));
    __nv_bfloat162 h0; h0.x = hx; h0.y = hy;
    __nv_bfloat162 h1; h1.x = hz; h1.y = hw;
    __nv_bfloat162 l0; l0.x = lx; l0.y = ly;
    __nv_bfloat162 l1; l1.x = lz; l1.y = lw;
    hi.x = *(uint32_t*)&h0; hi.y = *(uint32_t*)&h1;
    lo.x = *(uint32_t*)&l0; lo.y = *(uint32_t*)&l1;
}

__device__ __forceinline__ uint32_t pack2_hi(float a, float b) {
    __nv_bfloat162 h; h.x = __float2bfloat16(a); h.y = __float2bfloat16(b);
    return *(uint32_t*)&h;
}
__device__ __forceinline__ uint32_t pack2_lo(float a, float b) {
    __nv_bfloat16 ha = __float2bfloat16(a), hb = __float2bfloat16(b);
    __nv_bfloat162 l;
    l.x = __float2bfloat16(a - __bfloat162float(ha));
    l.y = __float2bfloat16(b - __bfloat162float(hb));
    return *(uint32_t*)&l;
}

// ---------------------------------------------------------------------------
// Weight split kernel: fp32 [total] -> split format. 4 elems/thread.
// ---------------------------------------------------------------------------
__global__ void __launch_bounds__(256) split_kernel(const float* __restrict__ src,
                                                    uint8_t* __restrict__ dst,
                                                    int total)
{
    const int e0 = (blockIdx.x * 256 + threadIdx.x) * 4;
    if (e0 >= total) return;
    const float4 v = *(const float4*)(src + e0);
    uint2 hi, lo;
    split4_pack(v, hi, lo);
    uint8_t* p = dst + (size_t)(e0 >> 5) * 128 + (e0 & 31) * 2;
    *(uint2*)(p)      = hi;
    *(uint2*)(p + 64) = lo;
}

// ---------------------------------------------------------------------------
// LayerNorm: one block per row; writes split format directly.
// ---------------------------------------------------------------------------
__global__ void __launch_bounds__(256) ln_kernel(const float* __restrict__ x,
                                                 const float* __restrict__ g,
                                                 const float* __restrict__ b,
                                                 uint8_t* __restrict__ y)
{
    const int row = blockIdx.x;
    const int tid = threadIdx.x;
    const float4 v = *(const float4*)(x + (size_t)row * DM + tid * 4);

    float s1 = v.x + v.y + v.z + v.w;
    float s2 = v.x*v.x + v.y*v.y + v.z*v.z + v.w*v.w;

    #pragma unroll
    for (int o = 16; o > 0; o >>= 1) {
        s1 += __shfl_xor_sync(0xffffffffu, s1, o);
        s2 += __shfl_xor_sync(0xffffffffu, s2, o);
    }
    __shared__ float r1[8], r2[8];
    if ((tid & 31) == 0) { r1[tid >> 5] = s1; r2[tid >> 5] = s2; }
    __syncthreads();
    float t1 = r1[tid & 7], t2 = r2[tid & 7];
    #pragma unroll
    for (int o = 4; o > 0; o >>= 1) {
        t1 += __shfl_xor_sync(0xffffffffu, t1, o);
        t2 += __shfl_xor_sync(0xffffffffu, t2, o);
    }
    const float mu  = t1 * (1.0f / DM);
    const float var = t2 * (1.0f / DM) - mu * mu;
    const float inv = rsqrtf(var + 1e-5f);

    const float4 gg = *(const float4*)(g + tid * 4);
    const float4 bb = *(const float4*)(b + tid * 4);
    float4 o4;
    o4.x = (v.x - mu) * inv * gg.x + bb.x;
    o4.y = (v.y - mu) * inv * gg.y + bb.y;
    o4.z = (v.z - mu) * inv * gg.z + bb.z;
    o4.w = (v.w - mu) * inv * gg.w + bb.w;

    uint2 hi, lo;
    split4_pack(o4, hi, lo);
    uint8_t* p = y + (size_t)row * DM * 4 + (tid >> 3) * 128 + (tid & 7) * 8;
    *(uint2*)(p)      = hi;
    *(uint2*)(p + 64) = lo;
}

// ---------------------------------------------------------------------------
// Tensor-core GEMM, pre-split bf16 operands, 4-stage cp.async pipeline.
// C[M,N] = A[M,K] @ B[N,K]^T (+epilogue). A,B in split format.
// 128x128 CTA tile, BK=32 fp32-equivalent, 256 threads = 8 warps (2m x 4n).
// EPI: 0 none, 1 +res, 2 +bias,gelu, 3 +bias,+res
// OSPLIT: write C in split format (Cs), else fp32 (C).
// ---------------------------------------------------------------------------
#define NSTAGES 4
#define STAGE_BYTES 32768        // A 16KB + B 16KB
#define GEMM_SMEM (NSTAGES * STAGE_BYTES)

template<int EPI, bool OSPLIT>
__global__ void __launch_bounds__(256) gemm_cp(const uint8_t* __restrict__ Aps,
                                               const uint8_t* __restrict__ Bps,
                                               const float* __restrict__ bias,
                                               const float* __restrict__ res,
                                               float* __restrict__ C,
                                               uint8_t* __restrict__ Cs,
                                               int M, int N, int K)
{
    extern __shared__ __align__(1024) char smem[];
    const uint32_t SU = smem_to_u32(smem);

    const int tid  = threadIdx.x;
    const int wid  = tid >> 5;
    const int lane = tid & 31;
    const int bm = blockIdx.y * 128;
    const int bn = blockIdx.x * 128;

    const int warpM = (wid >> 2) * 64;
    const int warpN = (wid & 3) * 32;

    const int aRow = ((lane >> 3) & 1) * 8 + (lane & 7);
    const int aCol = (lane >> 4) * 16;
    const int bRow = (lane >> 4) * 8 + (lane & 7);
    const int bCol = ((lane >> 3) & 1) * 16;

    const int g   = lane >> 2;
    const int tig = lane & 3;

    const size_t K4 = (size_t)K * 4;
    const uint8_t* Ab = Aps + (size_t)bm * K4;
    const uint8_t* Bb = Bps + (size_t)bn * K4;

    // per-thread copy indices: 4 chunks of 16B per operand per stage
    const int crow = tid >> 1;                 // wrong granularity; recompute below
    (void)crow;

    float acc[4][4][4];
    #pragma unroll
    for (int mt = 0; mt < 4; mt++)
        #pragma unroll
        for (int nt = 0; nt < 4; nt++)
            #pragma unroll
            for (int q = 0; q < 4; q++) acc[mt][nt][q] = 0.0f;

    const int NIT = K >> 5;

    // ---- issue one stage of async copies ----
    auto issue_stage = [&](int it, int stage) {
        const uint32_t base = SU + stage * STAGE_BYTES;
        #pragma unroll
        for (int i = 0; i < 4; i++) {
            const int c   = tid + i * 256;      // 0..1023
            const int row = c >> 3;
            const int seg = (c & 7) * 16;
            const uint32_t soff = SMEM_SWIZZLE_128B((uint32_t)(row * 128 + seg));
            cp_async16(base + soff,         Ab + (size_t)row * K4 + it * 128 + seg);
            cp_async16(base + 16384 + soff, Bb + (size_t)row * K4 + it * 128 + seg);
        }
    };

    // prologue
    #pragma unroll
    for (int s = 0; s < NSTAGES - 1; s++) {
        issue_stage(s, s);
        CP_COMMIT();
    }

    for (int it = 0; it < NIT; ++it) {
        CP_WAIT(NSTAGES - 2);
        __syncthreads();

        // refill the stage freed in iteration it-1 (safe after the barrier)
        if (it + NSTAGES - 1 < NIT)
            issue_stage(it + NSTAGES - 1, (it + NSTAGES - 1) & (NSTAGES - 1));
        CP_COMMIT();

        const uint32_t AsU = SU + (it & (NSTAGES - 1)) * STAGE_BYTES;
        const uint32_t BsU = AsU + 16384;

        #pragma unroll
        for (int s = 0; s < 2; s++) {
            const int kbH = s * 32;
            const int kbL = 64 + s * 32;

            uint32_t ahi[4][4], alo[4][4], bhi[2][4], blo[2][4];
            #pragma unroll
            for (int mt = 0; mt < 4; mt++) {
                const int r = warpM + mt * 16 + aRow;
                ldmatrix_x4(ahi[mt][0], ahi[mt][1], ahi[mt][2], ahi[mt][3],
                    AsU + SMEM_SWIZZLE_128B((uint32_t)(r * 128 + kbH + aCol)));
                ldmatrix_x4(alo[mt][0], alo[mt][1], alo[mt][2], alo[mt][3],
                    AsU + SMEM_SWIZZLE_128B((uint32_t)(r * 128 + kbL + aCol)));
            }
            #pragma unroll
            for (int p = 0; p < 2; p++) {
                const int r = warpN + p * 16 + bRow;
                ldmatrix_x4(bhi[p][0], bhi[p][1], bhi[p][2], bhi[p][3],
                    BsU + SMEM_SWIZZLE_128B((uint32_t)(r * 128 + kbH + bCol)));
                ldmatrix_x4(blo[p][0], blo[p][1], blo[p][2], blo[p][3],
                    BsU + SMEM_SWIZZLE_128B((uint32_t)(r * 128 + kbL + bCol)));
            }

            #pragma unroll
            for (int mt = 0; mt < 4; mt++)
                #pragma unroll
                for (int nt = 0; nt < 4; nt++) {
                    const uint32_t* bh = &bhi[nt >> 1][(nt & 1) * 2];
                    const uint32_t* bl = &blo[nt >> 1][(nt & 1) * 2];
                    mma_bf16(acc[mt][nt], ahi[mt], bh);
                    mma_bf16(acc[mt][nt], alo[mt], bh);
                    mma_bf16(acc[mt][nt], ahi[mt], bl);
                }
        }
        __syncthreads();
    }

    // ---- epilogue ----
    #pragma unroll
    for (int mt = 0; mt < 4; mt++) {
        #pragma unroll
        for (int nt = 0; nt < 4; nt++) {
            const int col = bn + warpN + nt * 8 + tig * 2;
            float v[4];
            #pragma unroll
            for (int q = 0; q < 4; q++) v[q] = acc[mt][nt][q];

            if (EPI == 2 || EPI == 3) {
                const float2 bv = *(const float2*)(bias + col);
                v[0] += bv.x; v[1] += bv.y; v[2] += bv.x; v[3] += bv.y;
            }
            if (EPI == 2) {
                #pragma unroll
                for (int q = 0; q < 4; q++)
                    v[q] = 0.5f * v[q] * (1.0f + erff(v[q] * 0.70710678118654752f));
            }
            const int row0 = bm + warpM + mt * 16 + g;
            const int row1 = row0 + 8;
            if (EPI == 1 || EPI == 3) {
                const float2 r0 = *(const float2*)(res + (size_t)row0 * N + col);
                const float2 r1 = *(const float2*)(res + (size_t)row1 * N + col);
                v[0] += r0.x; v[1] += r0.y; v[2] += r1.x; v[3] += r1.y;
            }
            if (OSPLIT) {
                uint8_t* p0 = Cs + (size_t)row0 * N * 4 + (col >> 5) * 128 + (col & 31) * 2;
                uint8_t* p1 = Cs + (size_t)row1 * N * 4 + (col >> 5) * 128 + (col & 31) * 2;
                *(uint32_t*)(p0)      = pack2_hi(v[0], v[1]);
                *(uint32_t*)(p0 + 64) = pack2_lo(v[0], v[1]);
                *(uint32_t*)(p1)      = pack2_hi(v[2], v[3]);
                *(uint32_t*)(p1 + 64) = pack2_lo(v[2], v[3]);
            } else {
                *(float2*)(C + (size_t)row0 * N + col) = make_float2(v[0], v[1]);
                *(float2*)(C + (size_t)row1 * N + col) = make_float2(v[2], v[3]);
            }
        }
    }
}

// ---------------------------------------------------------------------------
// Flash attention (fp32, causal). Writes split format output.
// ---------------------------------------------------------------------------
__global__ void __launch_bounds__(256) attn_kernel(const float* __restrict__ qkv,
                                                   uint8_t* __restrict__ outs)
{
    extern __shared__ float sm[];
    float* Qt = sm;             // [64][64]  Qt[d*64 + r], pre-scaled
    float* Kt = sm + 4096;      // [64][64]
    float* Vs = sm + 8192;      // [64][64]
    float* Pt = sm + 12288;     // [64][68]

    const int bh = blockIdx.x;
    const int rb = blockIdx.y;
    const int b  = bh >> 4;
    const int h  = bh & 15;

    const float* Qg = qkv + (size_t)(b * SEQ) * (3 * DM) + h * HD;
    const float* Kg = Qg + DM;
    const float* Vg = Qg + 2 * DM;

    const int tid = threadIdx.x;
    const int tr = tid >> 4, tc = tid & 15;
    const int r0 = tr * 4, c0 = tc * 4;

    {
        const int t = tid >> 2;
        const int dbase = (tid & 3) * 16;
        const float* src = Qg + (size_t)(rb * 64 + t) * (3 * DM) + dbase;
        #pragma unroll
        for (int j4 = 0; j4 < 4; j4++) {
            float4 v = *(const float4*)(src + j4 * 4);
            const int d = dbase + j4 * 4;
            Qt[(d + 0) * 64 + t] = v.x * 0.125f;
            Qt[(d + 1) * 64 + t] = v.y * 0.125f;
            Qt[(d + 2) * 64 + t] = v.z * 0.125f;
            Qt[(d + 3) * 64 + t] = v.w * 0.125f;
        }
    }

    float m[4], l[4], O[4][4];
    #pragma unroll
    for (int i = 0; i < 4; i++) {
        m[i] = -1e30f; l[i] = 0.0f;
        #pragma unroll
        for (int j = 0; j < 4; j++) O[i][j] = 0.0f;
    }

    for (int kb = 0; kb <= rb; kb++) {
        __syncthreads();
        {
            const int t = tid >> 2;
            const int dbase = (tid & 3) * 16;
            const float* ks = Kg + (size_t)(kb * 64 + t) * (3 * DM) + dbase;
            const float* vs = Vg + (size_t)(kb * 64 + t) * (3 * DM) + dbase;
            #pragma unroll
            for (int j4 = 0; j4 < 4; j4++) {
                float4 kv = *(const float4*)(ks + j4 * 4);
                const int d = dbase + j4 * 4;
                Kt[(d + 0) * 64 + t] = kv.x;
                Kt[(d + 1) * 64 + t] = kv.y;
                Kt[(d + 2) * 64 + t] = kv.z;
                Kt[(d + 3) * 64 + t] = kv.w;
                *(float4*)(Vs + t * 64 + d) = *(const float4*)(vs + j4 * 4);
            }
        }
        __syncthreads();

        float s[4][4];
        #pragma unroll
        for (int i = 0; i < 4; i++)
            #pragma unroll
            for (int j = 0; j < 4; j++) s[i][j] = 0.0f;
        #pragma unroll 16
        for (int d = 0; d < 64; d++) {
            float4 qv = *(const float4*)(Qt + d * 64 + r0);
            float4 kv = *(const float4*)(Kt + d * 64 + c0);
            const float qa[4] = {qv.x, qv.y, qv.z, qv.w};
            const float ka[4] = {kv.x, kv.y, kv.z, kv.w};
            #pragma unroll
            for (int i = 0; i < 4; i++)
                #pragma unroll
                for (int j = 0; j < 4; j++)
                    s[i][j] = fmaf(qa[i], ka[j], s[i][j]);
        }

        if (kb == rb) {
            #pragma unroll
            for (int i = 0; i < 4; i++)
                #pragma unroll
                for (int j = 0; j < 4; j++)
                    if (c0 + j > r0 + i) s[i][j] = -10000.0f;
        }

        #pragma unroll
        for (int i = 0; i < 4; i++) {
            float rm = fmaxf(fmaxf(s[i][0], s[i][1]), fmaxf(s[i][2], s[i][3]));
            #pragma unroll
            for (int o = 8; o > 0; o >>= 1)
                rm = fmaxf(rm, __shfl_xor_sync(0xffffffffu, rm, o));
            const float mn = fmaxf(m[i], rm);
            const float alpha = __expf(m[i] - mn);
            float rs = 0.0f;
            #pragma unroll
            for (int j = 0; j < 4; j++) {
                s[i][j] = __expf(s[i][j] - mn);
                rs += s[i][j];
            }
            #pragma unroll
            for (int o = 8; o > 0; o >>= 1)
                rs += __shfl_xor_sync(0xffffffffu, rs, o);
            l[i] = l[i] * alpha + rs;
            m[i] = mn;
            #pragma unroll
            for (int j = 0; j < 4; j++) O[i][j] *= alpha;
        }

        #pragma unroll
        for (int j = 0; j < 4; j++)
            #pragma unroll
            for (int i = 0; i < 4; i++)
                Pt[(c0 + j) * 68 + r0 + i] = s[i][j];
        __syncthreads();

        #pragma unroll 16
        for (int kc = 0; kc < 64; kc++) {
            float4 pv = *(const float4*)(Pt + kc * 68 + r0);
            float4 vv = *(const float4*)(Vs + kc * 64 + c0);
            const float pa[4] = {pv.x, pv.y, pv.z, pv.w};
            const float va[4] = {vv.x, vv.y, vv.z, vv.w};
            #pragma unroll
            for (int i = 0; i < 4; i++)
                #pragma unroll
                for (int j = 0; j < 4; j++)
                    O[i][j] = fmaf(pa[i], va[j], O[i][j]);
        }
    }

    const int col = h * HD + c0;
    #pragma unroll
    for (int i = 0; i < 4; i++) {
        const float inv = 1.0f / l[i];
        float4 o4;
        o4.x = O[i][0] * inv; o4.y = O[i][1] * inv;
        o4.z = O[i][2] * inv; o4.w = O[i][3] * inv;
        const size_t row = (size_t)(b * SEQ + rb * 64 + r0 + i);
        uint2 hi, lo;
        split4_pack(o4, hi, lo);
        uint8_t* p = outs + row * DM * 4 + (col >> 5) * 128 + (col & 31) * 2;
        *(uint2*)(p)      = hi;
        *(uint2*)(p + 64) = lo;
    }
}

// ---------------------------------------------------------------------------
extern "C" void kernel_launch(void* const* d_in, const int* in_sizes, int n_in,
                              void* d_out, int out_size)
{
    const float* x      = (const float*)d_in[0];
    const float* w_qkv  = (const float*)d_in[1];
    const float* w_proj = (const float*)d_in[2];
    const float* w_ff1  = (const float*)d_in[3];
    const float* b_ff1  = (const float*)d_in[4];
    const float* w_ff2  = (const float*)d_in[5];
    const float* b_ff2  = (const float*)d_in[6];
    const float* ln1_g  = (const float*)d_in[7];
    const float* ln1_b  = (const float*)d_in[8];
    const float* ln2_g  = (const float*)d_in[9];
    const float* ln2_b  = (const float*)d_in[10];
    float* out = (float*)d_out;

    uint8_t *p_lns, *p_atts, *p_ffs, *p_wqkv, *p_wprj, *p_wff1, *p_wff2;
    float *p_qkv, *p_x1;
    cudaGetSymbolAddress((void**)&p_lns,  g_lns);
    cudaGetSymbolAddress((void**)&p_qkv,  g_qkv);
    cudaGetSymbolAddress((void**)&p_atts, g_atts);
    cudaGetSymbolAddress((void**)&p_x1,   g_x1);
    cudaGetSymbolAddress((void**)&p_ffs,  g_ffs);
    cudaGetSymbolAddress((void**)&p_wqkv, g_wqkv);
    cudaGetSymbolAddress((void**)&p_wprj, g_wprj);
    cudaGetSymbolAddress((void**)&p_wff1, g_wff1);
    cudaGetSymbolAddress((void**)&p_wff2, g_wff2);

    const int ATTN_SMEM = (4096 * 3 + 64 * 68) * 4;   // 66560 B
    cudaFuncSetAttribute(attn_kernel,
                         cudaFuncAttributeMaxDynamicSharedMemorySize, ATTN_SMEM);
    cudaFuncSetAttribute(gemm_cp<0, false>,
                         cudaFuncAttributeMaxDynamicSharedMemorySize, GEMM_SMEM);
    cudaFuncSetAttribute(gemm_cp<1, false>,
                         cudaFuncAttributeMaxDynamicSharedMemorySize, GEMM_SMEM);
    cudaFuncSetAttribute(gemm_cp<2, true>,
                         cudaFuncAttributeMaxDynamicSharedMemorySize, GEMM_SMEM);
    cudaFuncSetAttribute(gemm_cp<3, false>,
                         cudaFuncAttributeMaxDynamicSharedMemorySize, GEMM_SMEM);

    // 0. split weights (independent of activations)
    split_kernel<<<3 * DM * DM / 1024, 256>>>(w_qkv,  p_wqkv, 3 * DM * DM);
    split_kernel<<<DM * DM / 1024, 256>>>(w_proj, p_wprj, DM * DM);
    split_kernel<<<DFF * DM / 1024, 256>>>(w_ff1,  p_wff1, DFF * DM);
    split_kernel<<<DM * DFF / 1024, 256>>>(w_ff2,  p_wff2, DM * DFF);

    // 1. LN1 (split output)
    ln_kernel<<<MTOK, 256>>>(x, ln1_g, ln1_b, p_lns);
    // 2. QKV projection: [8192,3072] fp32 out
    gemm_cp<0, false><<<dim3(3 * DM / 128, MTOK / 128), 256, GEMM_SMEM>>>(
        p_lns, p_wqkv, nullptr, nullptr, p_qkv, nullptr, MTOK, 3 * DM, DM);
    // 3. causal flash attention (split output)
    attn_kernel<<<dim3(BATCH * NHEADS, SEQ / 64), 256, ATTN_SMEM>>>(p_qkv, p_atts);
    // 4. out projection + residual: x1 = x + att @ Wp^T (fp32 out)
    gemm_cp<1, false><<<dim3(DM / 128, MTOK / 128), 256, GEMM_SMEM>>>(
        p_atts, p_wprj, nullptr, x, p_x1, nullptr, MTOK, DM, DM);
    // 5. LN2 (split output)
    ln_kernel<<<MTOK, 256>>>(p_x1, ln2_g, ln2_b, p_lns);
    // 6. FF1 + bias + exact GELU (split output)
    gemm_cp<2, true><<<dim3(DFF / 128, MTOK / 128), 256, GEMM_SMEM>>>(
        p_lns, p_wff1, b_ff1, nullptr, nullptr, p_ffs, MTOK, DFF, DM);
    // 7. FF2 + bias + residual -> out (fp32)
    gemm_cp<3, false><<<dim3(DM / 128, MTOK / 128), 256, GEMM_SMEM>>>(
        p_ffs, p_wff2, b_ff2, p_x1, out, nullptr, MTOK, DM, DFF);
}

// round 8
// speedup vs baseline: 2.9244x; 1.1301x over previous
#include <cuda_runtime.h>
#include <cuda_bf16.h>
#include <math.h>
#include <cstdint>

// Problem dims (fixed by reference)
#define BATCH   16
#define SEQ     512
#define DM      1024
#define NHEADS  16
#define HD      64
#define DFF     4096
#define MTOK    (BATCH*SEQ)          // 8192 rows

// ---------------- scratch (device globals; no allocations allowed) ---------
// "split format": per logical row of K fp32, K/32 blocks of 128B:
// [32 hi bf16 | 32 lo bf16]. Element (r,k): base + r*K*4 + (k>>5)*128 +
// (k&31)*2 (hi), +64 (lo).
__device__ uint8_t g_lns [MTOK * DM * 4];        // ln1/ln2 out (split)
__device__ float   g_qkv [MTOK * 3 * DM];        // qkv projections (fp32)
__device__ uint8_t g_atts[MTOK * DM * 4];        // attention out (split)
__device__ float   g_x1  [MTOK * DM];            // residual after attention
__device__ uint8_t g_ffs [MTOK * DFF * 4];       // ff1 activations (split)
__device__ uint8_t g_wqkv[3 * DM * DM * 4];      // split weights
__device__ uint8_t g_wprj[DM * DM * 4];
__device__ uint8_t g_wff1[DFF * DM * 4];
__device__ uint8_t g_wff2[DM * DFF * 4];

#define SMEM_SWIZZLE_128B(byte_offset) \
    ((byte_offset) ^ (((byte_offset) >> 3) & 0x70))

__device__ __forceinline__ uint32_t smem_to_u32(const void* smem_ptr) {
    uint32_t addr;
    asm("{ .reg .u64 tmp; cvta.to.shared.u64 tmp, %1; cvt.u32.u64 %0, tmp; }"
        : "=r"(addr) : "l"(smem_ptr));
    return addr;
}

__device__ __forceinline__ void cp_async16(uint32_t dst, const void* src) {
    asm volatile("cp.async.ca.shared.global [%0], [%1], 16;"
                 :: "r"(dst), "l"(src));
}
#define CP_COMMIT() asm volatile("cp.async.commit_group;" ::: "memory")
#define CP_WAIT(n)  asm volatile("cp.async.wait_group %0;" :: "n"(n) : "memory")

__device__ __forceinline__ void ldmatrix_x4(uint32_t& r0, uint32_t& r1,
                                            uint32_t& r2, uint32_t& r3,
                                            uint32_t addr) {
    asm volatile("ldmatrix.sync.aligned.m8n8.x4.shared.b16 {%0,%1,%2,%3}, [%4];"
                 : "=r"(r0), "=r"(r1), "=r"(r2), "=r"(r3) : "r"(addr));
}

__device__ __forceinline__ void mma_bf16(float* c, const uint32_t* a,
                                         const uint32_t* b) {
    asm volatile(
        "mma.sync.aligned.m16n8k16.row.col.f32.bf16.bf16.f32 "
        "{%0,%1,%2,%3}, {%4,%5,%6,%7}, {%8,%9}, {%0,%1,%2,%3};"
        : "+f"(c[0]), "+f"(c[1]), "+f"(c[2]), "+f"(c[3])
        : "r"(a[0]), "r"(a[1]), "r"(a[2]), "r"(a[3]), "r"(b[0]), "r"(b[1]));
}

__device__ __forceinline__ void split4_pack(const float4 v, uint2& hi, uint2& lo) {
    __nv_bfloat16 hx = __float2bfloat16(v.x);
    __nv_bfloat16 hy = __float2bfloat16(v.y);
    __nv_bfloat16 hz = __float2bfloat16(v.z);
    __nv_bfloat16 hw = __float2bfloat16(v.w);
    __nv_bfloat16 lx = __float2bfloat16(v.x - __bfloat162float(hx));
    __nv_bfloat16 ly = __float2bfloat16(v.y - __bfloat162float(hy));
    __nv_bfloat16 lz = __float2bfloat16(v.z - __bfloat162float(hz));
    __nv_bfloat16 lw = __float2bfloat16(v.w - __bfloat162float(hw));
    __nv_bfloat162 h0; h0.x = hx; h0.y = hy;
    __nv_bfloat162 h1; h1.x = hz; h1.y = hw;
    __nv_bfloat162 l0; l0.x = lx; l0.y = ly;
    __nv_bfloat162 l1; l1.x = lz; l1.y = lw;
    hi.x = *(uint32_t*)&h0; hi.y = *(uint32_t*)&h1;
    lo.x = *(uint32_t*)&l0; lo.y = *(uint32_t*)&l1;
}

__device__ __forceinline__ uint32_t pack2_hi(float a, float b) {
    __nv_bfloat162 h; h.x = __float2bfloat16(a); h.y = __float2bfloat16(b);
    return *(uint32_t*)&h;
}
__device__ __forceinline__ uint32_t pack2_lo(float a, float b) {
    __nv_bfloat16 ha = __float2bfloat16(a), hb = __float2bfloat16(b);
    __nv_bfloat162 l;
    l.x = __float2bfloat16(a - __bfloat162float(ha));
    l.y = __float2bfloat16(b - __bfloat162float(hb));
    return *(uint32_t*)&l;
}
__device__ __forceinline__ uint16_t bhi16(float x) {
    __nv_bfloat16 h = __float2bfloat16(x); return *(uint16_t*)&h;
}
__device__ __forceinline__ uint16_t blo16(float x) {
    __nv_bfloat16 h = __float2bfloat16(x);
    __nv_bfloat16 l = __float2bfloat16(x - __bfloat162float(h));
    return *(uint16_t*)&l;
}

// ---------------------------------------------------------------------------
// Weight split kernel
// ---------------------------------------------------------------------------
__global__ void __launch_bounds__(256) split_kernel(const float* __restrict__ src,
                                                    uint8_t* __restrict__ dst,
                                                    int total)
{
    const int e0 = (blockIdx.x * 256 + threadIdx.x) * 4;
    if (e0 >= total) return;
    const float4 v = *(const float4*)(src + e0);
    uint2 hi, lo;
    split4_pack(v, hi, lo);
    uint8_t* p = dst + (size_t)(e0 >> 5) * 128 + (e0 & 31) * 2;
    *(uint2*)(p)      = hi;
    *(uint2*)(p + 64) = lo;
}

// ---------------------------------------------------------------------------
// LayerNorm: one block per row; writes split format directly.
// ---------------------------------------------------------------------------
__global__ void __launch_bounds__(256) ln_kernel(const float* __restrict__ x,
                                                 const float* __restrict__ g,
                                                 const float* __restrict__ b,
                                                 uint8_t* __restrict__ y)
{
    const int row = blockIdx.x;
    const int tid = threadIdx.x;
    const float4 v = *(const float4*)(x + (size_t)row * DM + tid * 4);

    float s1 = v.x + v.y + v.z + v.w;
    float s2 = v.x*v.x + v.y*v.y + v.z*v.z + v.w*v.w;

    #pragma unroll
    for (int o = 16; o > 0; o >>= 1) {
        s1 += __shfl_xor_sync(0xffffffffu, s1, o);
        s2 += __shfl_xor_sync(0xffffffffu, s2, o);
    }
    __shared__ float r1[8], r2[8];
    if ((tid & 31) == 0) { r1[tid >> 5] = s1; r2[tid >> 5] = s2; }
    __syncthreads();
    float t1 = r1[tid & 7], t2 = r2[tid & 7];
    #pragma unroll
    for (int o = 4; o > 0; o >>= 1) {
        t1 += __shfl_xor_sync(0xffffffffu, t1, o);
        t2 += __shfl_xor_sync(0xffffffffu, t2, o);
    }
    const float mu  = t1 * (1.0f / DM);
    const float var = t2 * (1.0f / DM) - mu * mu;
    const float inv = rsqrtf(var + 1e-5f);

    const float4 gg = *(const float4*)(g + tid * 4);
    const float4 bb = *(const float4*)(b + tid * 4);
    float4 o4;
    o4.x = (v.x - mu) * inv * gg.x + bb.x;
    o4.y = (v.y - mu) * inv * gg.y + bb.y;
    o4.z = (v.z - mu) * inv * gg.z + bb.z;
    o4.w = (v.w - mu) * inv * gg.w + bb.w;

    uint2 hi, lo;
    split4_pack(o4, hi, lo);
    uint8_t* p = y + (size_t)row * DM * 4 + (tid >> 3) * 128 + (tid & 7) * 8;
    *(uint2*)(p)      = hi;
    *(uint2*)(p + 64) = lo;
}

// ---------------------------------------------------------------------------
// Tensor-core GEMM, pre-split bf16 operands, 3-stage cp.async pipeline,
// 2 CTAs/SM. C[M,N] = A[M,K] @ B[N,K]^T (+epilogue).
// ---------------------------------------------------------------------------
#define NSTAGES 3
#define STAGE_BYTES 32768        // A 16KB + B 16KB
#define GEMM_SMEM (NSTAGES * STAGE_BYTES)

template<int EPI, bool OSPLIT>
__global__ void __launch_bounds__(256, 2) gemm_cp(const uint8_t* __restrict__ Aps,
                                                  const uint8_t* __restrict__ Bps,
                                                  const float* __restrict__ bias,
                                                  const float* __restrict__ res,
                                                  float* __restrict__ C,
                                                  uint8_t* __restrict__ Cs,
                                                  int M, int N, int K)
{
    extern __shared__ __align__(1024) char smem[];
    const uint32_t SU = smem_to_u32(smem);

    const int tid  = threadIdx.x;
    const int wid  = tid >> 5;
    const int lane = tid & 31;
    const int bm = blockIdx.y * 128;
    const int bn = blockIdx.x * 128;

    const int warpM = (wid >> 2) * 64;
    const int warpN = (wid & 3) * 32;

    const int aRow = ((lane >> 3) & 1) * 8 + (lane & 7);
    const int aCol = (lane >> 4) * 16;
    const int bRow = (lane >> 4) * 8 + (lane & 7);
    const int bCol = ((lane >> 3) & 1) * 16;

    const int g   = lane >> 2;
    const int tig = lane & 3;

    const size_t K4 = (size_t)K * 4;
    const uint8_t* Ab = Aps + (size_t)bm * K4;
    const uint8_t* Bb = Bps + (size_t)bn * K4;

    float acc[4][4][4];
    #pragma unroll
    for (int mt = 0; mt < 4; mt++)
        #pragma unroll
        for (int nt = 0; nt < 4; nt++)
            #pragma unroll
            for (int q = 0; q < 4; q++) acc[mt][nt][q] = 0.0f;

    const int NIT = K >> 5;

    auto issue_stage = [&](int it, int stage) {
        const uint32_t base = SU + stage * STAGE_BYTES;
        #pragma unroll
        for (int i = 0; i < 4; i++) {
            const int c   = tid + i * 256;
            const int row = c >> 3;
            const int seg = (c & 7) * 16;
            const uint32_t soff = SMEM_SWIZZLE_128B((uint32_t)(row * 128 + seg));
            cp_async16(base + soff,         Ab + (size_t)row * K4 + it * 128 + seg);
            cp_async16(base + 16384 + soff, Bb + (size_t)row * K4 + it * 128 + seg);
        }
    };

    #pragma unroll
    for (int s = 0; s < NSTAGES - 1; s++) {
        issue_stage(s, s);
        CP_COMMIT();
    }

    int ld_it = NSTAGES - 1;
    int ld_stage = NSTAGES - 1;
    int cm_stage = 0;

    for (int it = 0; it < NIT; ++it) {
        CP_WAIT(NSTAGES - 2);
        __syncthreads();

        if (ld_it < NIT) issue_stage(ld_it, ld_stage);
        CP_COMMIT();
        ld_it++;
        ld_stage = (ld_stage + 1 == NSTAGES) ? 0 : ld_stage + 1;

        const uint32_t AsU = SU + cm_stage * STAGE_BYTES;
        const uint32_t BsU = AsU + 16384;
        cm_stage = (cm_stage + 1 == NSTAGES) ? 0 : cm_stage + 1;

        #pragma unroll
        for (int s = 0; s < 2; s++) {
            const int kbH = s * 32;
            const int kbL = 64 + s * 32;

            uint32_t ahi[4][4], alo[4][4], bhi[2][4], blo[2][4];
            #pragma unroll
            for (int mt = 0; mt < 4; mt++) {
                const int r = warpM + mt * 16 + aRow;
                ldmatrix_x4(ahi[mt][0], ahi[mt][1], ahi[mt][2], ahi[mt][3],
                    AsU + SMEM_SWIZZLE_128B((uint32_t)(r * 128 + kbH + aCol)));
                ldmatrix_x4(alo[mt][0], alo[mt][1], alo[mt][2], alo[mt][3],
                    AsU + SMEM_SWIZZLE_128B((uint32_t)(r * 128 + kbL + aCol)));
            }
            #pragma unroll
            for (int p = 0; p < 2; p++) {
                const int r = warpN + p * 16 + bRow;
                ldmatrix_x4(bhi[p][0], bhi[p][1], bhi[p][2], bhi[p][3],
                    BsU + SMEM_SWIZZLE_128B((uint32_t)(r * 128 + kbH + bCol)));
                ldmatrix_x4(blo[p][0], blo[p][1], blo[p][2], blo[p][3],
                    BsU + SMEM_SWIZZLE_128B((uint32_t)(r * 128 + kbL + bCol)));
            }

            #pragma unroll
            for (int mt = 0; mt < 4; mt++)
                #pragma unroll
                for (int nt = 0; nt < 4; nt++) {
                    const uint32_t* bh = &bhi[nt >> 1][(nt & 1) * 2];
                    const uint32_t* bl = &blo[nt >> 1][(nt & 1) * 2];
                    mma_bf16(acc[mt][nt], ahi[mt], bh);
                    mma_bf16(acc[mt][nt], alo[mt], bh);
                    mma_bf16(acc[mt][nt], ahi[mt], bl);
                }
        }
        __syncthreads();
    }

    // ---- epilogue ----
    #pragma unroll
    for (int mt = 0; mt < 4; mt++) {
        #pragma unroll
        for (int nt = 0; nt < 4; nt++) {
            const int col = bn + warpN + nt * 8 + tig * 2;
            float v[4];
            #pragma unroll
            for (int q = 0; q < 4; q++) v[q] = acc[mt][nt][q];

            if (EPI == 2 || EPI == 3) {
                const float2 bv = *(const float2*)(bias + col);
                v[0] += bv.x; v[1] += bv.y; v[2] += bv.x; v[3] += bv.y;
            }
            if (EPI == 2) {
                #pragma unroll
                for (int q = 0; q < 4; q++)
                    v[q] = 0.5f * v[q] * (1.0f + erff(v[q] * 0.70710678118654752f));
            }
            const int row0 = bm + warpM + mt * 16 + g;
            const int row1 = row0 + 8;
            if (EPI == 1 || EPI == 3) {
                const float2 r0 = *(const float2*)(res + (size_t)row0 * N + col);
                const float2 r1 = *(const float2*)(res + (size_t)row1 * N + col);
                v[0] += r0.x; v[1] += r0.y; v[2] += r1.x; v[3] += r1.y;
            }
            if (OSPLIT) {
                uint8_t* p0 = Cs + (size_t)row0 * N * 4 + (col >> 5) * 128 + (col & 31) * 2;
                uint8_t* p1 = Cs + (size_t)row1 * N * 4 + (col >> 5) * 128 + (col & 31) * 2;
                *(uint32_t*)(p0)      = pack2_hi(v[0], v[1]);
                *(uint32_t*)(p0 + 64) = pack2_lo(v[0], v[1]);
                *(uint32_t*)(p1)      = pack2_hi(v[2], v[3]);
                *(uint32_t*)(p1 + 64) = pack2_lo(v[2], v[3]);
            } else {
                *(float2*)(C + (size_t)row0 * N + col) = make_float2(v[0], v[1]);
                *(float2*)(C + (size_t)row1 * N + col) = make_float2(v[2], v[3]);
            }
        }
    }
}

// ---------------------------------------------------------------------------
// Flash attention on tensor cores (3x-split bf16). Causal.
// One CTA = one (b,h) x 128 query rows. 8 warps, each warp 16 q-rows x full
// 64-key tile. Q/K/V converted to split-bf16 smem planes on load; V stored
// transposed (rows = head dim, k = keys).
// smem: Q 2 planes x 128 rows x 128B = 32KB @0
//       K 2 planes x  64 rows x 128B = 16KB @32768
//       V 2 planes x  64 rows x 128B = 16KB @49152   (total 64KB)
// ---------------------------------------------------------------------------
#define ATT_SMEM 65536

__global__ void __launch_bounds__(256, 2) attn_mma(const float* __restrict__ qkv,
                                                   uint8_t* __restrict__ outs)
{
    extern __shared__ __align__(1024) uint8_t asmem[];
    const uint32_t SU = smem_to_u32(asmem);
    const uint32_t QU = SU;
    const uint32_t KU = SU + 32768;
    const uint32_t VU = SU + 49152;

    const int bh = blockIdx.x;          // 0..255
    const int qb = blockIdx.y;          // 0..3  (128 q rows each)
    const int b  = bh >> 4;
    const int h  = bh & 15;

    const int tid  = threadIdx.x;
    const int wid  = tid >> 5;
    const int lane = tid & 31;
    const int g    = lane >> 2;
    const int tig  = lane & 3;

    const int aRow = ((lane >> 3) & 1) * 8 + (lane & 7);
    const int aCol = (lane >> 4) * 16;
    const int bRow = (lane >> 4) * 8 + (lane & 7);
    const int bCol = ((lane >> 3) & 1) * 16;

    const float* base = qkv + (size_t)(b * SEQ) * (3 * DM) + h * HD;

    // ---- load Q block (scaled by 1/8), split into 2 d-planes ----
    #pragma unroll
    for (int i = 0; i < 8; i++) {
        const int idx = tid + i * 256;        // float4 index, 2048 total
        const int row = idx >> 4;             // 0..127
        const int d0  = (idx & 15) * 4;       // 0..60
        float4 v = *(const float4*)(base + (size_t)(qb * 128 + row) * (3 * DM) + d0);
        v.x *= 0.125f; v.y *= 0.125f; v.z *= 0.125f; v.w *= 0.125f;
        uint2 hi, lo;
        split4_pack(v, hi, lo);
        const uint32_t pl = (d0 >> 5) * 16384;
        const uint32_t c2 = (d0 & 31) * 2;
        *(uint2*)(asmem + (pl + SMEM_SWIZZLE_128B((uint32_t)(row * 128 + c2))))      = hi;
        *(uint2*)(asmem + (pl + SMEM_SWIZZLE_128B((uint32_t)(row * 128 + 64 + c2)))) = lo;
    }

    float m[2]  = {-1e30f, -1e30f};
    float l[2]  = {0.0f, 0.0f};
    float O[8][4];
    #pragma unroll
    for (int nt = 0; nt < 8; nt++)
        #pragma unroll
        for (int q = 0; q < 4; q++) O[nt][q] = 0.0f;

    const int kbmax = qb * 2 + 1;
    const int qrow0 = qb * 128 + wid * 16 + g;      // row for c0,c1
    for (int kb = 0; kb <= kbmax; kb++) {
        __syncthreads();
        // ---- load K (row=key, split planes) and V^T (row=d, key planes) ----
        #pragma unroll
        for (int i = 0; i < 4; i++) {
            const int idx = tid + i * 256;        // 1024 float4
            const int key = idx >> 4;             // 0..63
            const int d0  = (idx & 15) * 4;
            const size_t grow = (size_t)(kb * 64 + key) * (3 * DM);
            // K
            {
                float4 v = *(const float4*)(base + DM + grow + d0);
                uint2 hi, lo;
                split4_pack(v, hi, lo);
                const uint32_t pl = 32768 + (d0 >> 5) * 8192;
                const uint32_t c2 = (d0 & 31) * 2;
                *(uint2*)(asmem + (pl + SMEM_SWIZZLE_128B((uint32_t)(key * 128 + c2))))      = hi;
                *(uint2*)(asmem + (pl + SMEM_SWIZZLE_128B((uint32_t)(key * 128 + 64 + c2)))) = lo;
            }
            // V transposed: dest row = d, col = key
            {
                float4 v = *(const float4*)(base + 2 * DM + grow + d0);
                const uint32_t pl = 49152 + (key >> 5) * 8192;
                const uint32_t kc = (key & 31) * 2;
                const float vv[4] = {v.x, v.y, v.z, v.w};
                #pragma unroll
                for (int j = 0; j < 4; j++) {
                    const int d = d0 + j;
                    const uint32_t oh = pl + SMEM_SWIZZLE_128B((uint32_t)(d * 128 + kc));
                    const uint32_t ol = pl + SMEM_SWIZZLE_128B((uint32_t)(d * 128 + 64 + kc));
                    *(uint16_t*)(asmem + oh) = bhi16(vv[j]);
                    *(uint16_t*)(asmem + ol) = blo16(vv[j]);
                }
            }
        }
        __syncthreads();

        // ---- S = Q K^T  (warp: 16 q-rows x 64 keys), 3-pass split ----
        float sacc[8][4];
        #pragma unroll
        for (int nt = 0; nt < 8; nt++)
            #pragma unroll
            for (int q = 0; q < 4; q++) sacc[nt][q] = 0.0f;

        #pragma unroll
        for (int s = 0; s < 4; s++) {           // k16 over d
            const uint32_t qpl = QU + (s >> 1) * 16384;
            const int kbH = (s & 1) * 32;
            const int kbL = 64 + (s & 1) * 32;
            const int ra = wid * 16 + aRow;
            uint32_t ahi[4], alo[4];
            ldmatrix_x4(ahi[0], ahi[1], ahi[2], ahi[3],
                qpl + SMEM_SWIZZLE_128B((uint32_t)(ra * 128 + kbH + aCol)));
            ldmatrix_x4(alo[0], alo[1], alo[2], alo[3],
                qpl + SMEM_SWIZZLE_128B((uint32_t)(ra * 128 + kbL + aCol)));

            const uint32_t kpl = KU + (s >> 1) * 8192;
            #pragma unroll
            for (int p = 0; p < 4; p++) {       // key n8-tile pairs
                const int r = p * 16 + bRow;
                uint32_t bhi[4], blo[4];
                ldmatrix_x4(bhi[0], bhi[1], bhi[2], bhi[3],
                    kpl + SMEM_SWIZZLE_128B((uint32_t)(r * 128 + kbH + bCol)));
                ldmatrix_x4(blo[0], blo[1], blo[2], blo[3],
                    kpl + SMEM_SWIZZLE_128B((uint32_t)(r * 128 + kbL + bCol)));
                #pragma unroll
                for (int u = 0; u < 2; u++) {
                    const int nt = p * 2 + u;
                    mma_bf16(sacc[nt], ahi, &bhi[u * 2]);
                    mma_bf16(sacc[nt], alo, &bhi[u * 2]);
                    mma_bf16(sacc[nt], ahi, &blo[u * 2]);
                }
            }
        }

        // ---- causal mask (only where the key block can exceed q rows) ----
        if (kb >= qb * 2) {
            #pragma unroll
            for (int nt = 0; nt < 8; nt++) {
                const int col = kb * 64 + nt * 8 + tig * 2;
                if (col     > qrow0)     sacc[nt][0] = -10000.0f;
                if (col + 1 > qrow0)     sacc[nt][1] = -10000.0f;
                if (col     > qrow0 + 8) sacc[nt][2] = -10000.0f;
                if (col + 1 > qrow0 + 8) sacc[nt][3] = -10000.0f;
            }
        }

        // ---- online softmax (2 rows per thread) ----
        #pragma unroll
        for (int rh = 0; rh < 2; rh++) {
            const int q0 = rh * 2;
            float rm = -1e30f;
            #pragma unroll
            for (int nt = 0; nt < 8; nt++)
                rm = fmaxf(rm, fmaxf(sacc[nt][q0], sacc[nt][q0 + 1]));
            rm = fmaxf(rm, __shfl_xor_sync(0xffffffffu, rm, 1));
            rm = fmaxf(rm, __shfl_xor_sync(0xffffffffu, rm, 2));
            const float mn = fmaxf(m[rh], rm);
            const float alpha = __expf(m[rh] - mn);
            float rs = 0.0f;
            #pragma unroll
            for (int nt = 0; nt < 8; nt++) {
                sacc[nt][q0]     = __expf(sacc[nt][q0] - mn);
                sacc[nt][q0 + 1] = __expf(sacc[nt][q0 + 1] - mn);
                rs += sacc[nt][q0] + sacc[nt][q0 + 1];
            }
            rs += __shfl_xor_sync(0xffffffffu, rs, 1);
            rs += __shfl_xor_sync(0xffffffffu, rs, 2);
            l[rh] = l[rh] * alpha + rs;
            m[rh] = mn;
            #pragma unroll
            for (int nt = 0; nt < 8; nt++) {
                O[nt][q0]     *= alpha;
                O[nt][q0 + 1] *= alpha;
            }
        }

        // ---- O += P V  (P from register fragments, V^T from smem) ----
        #pragma unroll
        for (int s = 0; s < 4; s++) {           // k16 over keys
            uint32_t phi[4], plo[4];
            phi[0] = pack2_hi(sacc[2*s][0],   sacc[2*s][1]);
            phi[1] = pack2_hi(sacc[2*s][2],   sacc[2*s][3]);
            phi[2] = pack2_hi(sacc[2*s+1][0], sacc[2*s+1][1]);
            phi[3] = pack2_hi(sacc[2*s+1][2], sacc[2*s+1][3]);
            plo[0] = pack2_lo(sacc[2*s][0],   sacc[2*s][1]);
            plo[1] = pack2_lo(sacc[2*s][2],   sacc[2*s][3]);
            plo[2] = pack2_lo(sacc[2*s+1][0], sacc[2*s+1][1]);
            plo[3] = pack2_lo(sacc[2*s+1][2], sacc[2*s+1][3]);

            const uint32_t vpl = VU + (s >> 1) * 8192;
            const int kbH = (s & 1) * 32;
            const int kbL = 64 + (s & 1) * 32;
            #pragma unroll
            for (int p = 0; p < 4; p++) {       // d n8-tile pairs
                const int r = p * 16 + bRow;
                uint32_t vhi[4], vlo[4];
                ldmatrix_x4(vhi[0], vhi[1], vhi[2], vhi[3],
                    vpl + SMEM_SWIZZLE_128B((uint32_t)(r * 128 + kbH + bCol)));
                ldmatrix_x4(vlo[0], vlo[1], vlo[2], vlo[3],
                    vpl + SMEM_SWIZZLE_128B((uint32_t)(r * 128 + kbL + bCol)));
                #pragma unroll
                for (int u = 0; u < 2; u++) {
                    const int nt = p * 2 + u;
                    mma_bf16(O[nt], phi, &vhi[u * 2]);
                    mma_bf16(O[nt], plo, &vhi[u * 2]);
                    mma_bf16(O[nt], phi, &vlo[u * 2]);
                }
            }
        }
    }

    // ---- epilogue: normalize, write split-format attention output ----
    const float inv0 = 1.0f / l[0];
    const float inv1 = 1.0f / l[1];
    const size_t grow0 = (size_t)(b * SEQ + qb * 128 + wid * 16 + g);
    #pragma unroll
    for (int nt = 0; nt < 8; nt++) {
        const int col = h * HD + nt * 8 + tig * 2;
        uint8_t* p0 = outs + grow0 * DM * 4 + (col >> 5) * 128 + (col & 31) * 2;
        uint8_t* p1 = outs + (grow0 + 8) * DM * 4 + (col >> 5) * 128 + (col & 31) * 2;
        const float v0 = O[nt][0] * inv0, v1 = O[nt][1] * inv0;
        const float v2 = O[nt][2] * inv1, v3 = O[nt][3] * inv1;
        *(uint32_t*)(p0)      = pack2_hi(v0, v1);
        *(uint32_t*)(p0 + 64) = pack2_lo(v0, v1);
        *(uint32_t*)(p1)      = pack2_hi(v2, v3);
        *(uint32_t*)(p1 + 64) = pack2_lo(v2, v3);
    }
}

// ---------------------------------------------------------------------------
extern "C" void kernel_launch(void* const* d_in, const int* in_sizes, int n_in,
                              void* d_out, int out_size)
{
    const float* x      = (const float*)d_in[0];
    const float* w_qkv  = (const float*)d_in[1];
    const float* w_proj = (const float*)d_in[2];
    const float* w_ff1  = (const float*)d_in[3];
    const float* b_ff1  = (const float*)d_in[4];
    const float* w_ff2  = (const float*)d_in[5];
    const float* b_ff2  = (const float*)d_in[6];
    const float* ln1_g  = (const float*)d_in[7];
    const float* ln1_b  = (const float*)d_in[8];
    const float* ln2_g  = (const float*)d_in[9];
    const float* ln2_b  = (const float*)d_in[10];
    float* out = (float*)d_out;

    uint8_t *p_lns, *p_atts, *p_ffs, *p_wqkv, *p_wprj, *p_wff1, *p_wff2;
    float *p_qkv, *p_x1;
    cudaGetSymbolAddress((void**)&p_lns,  g_lns);
    cudaGetSymbolAddress((void**)&p_qkv,  g_qkv);
    cudaGetSymbolAddress((void**)&p_atts, g_atts);
    cudaGetSymbolAddress((void**)&p_x1,   g_x1);
    cudaGetSymbolAddress((void**)&p_ffs,  g_ffs);
    cudaGetSymbolAddress((void**)&p_wqkv, g_wqkv);
    cudaGetSymbolAddress((void**)&p_wprj, g_wprj);
    cudaGetSymbolAddress((void**)&p_wff1, g_wff1);
    cudaGetSymbolAddress((void**)&p_wff2, g_wff2);

    cudaFuncSetAttribute(attn_mma,
                         cudaFuncAttributeMaxDynamicSharedMemorySize, ATT_SMEM);
    cudaFuncSetAttribute(gemm_cp<0, false>,
                         cudaFuncAttributeMaxDynamicSharedMemorySize, GEMM_SMEM);
    cudaFuncSetAttribute(gemm_cp<1, false>,
                         cudaFuncAttributeMaxDynamicSharedMemorySize, GEMM_SMEM);
    cudaFuncSetAttribute(gemm_cp<2, true>,
                         cudaFuncAttributeMaxDynamicSharedMemorySize, GEMM_SMEM);
    cudaFuncSetAttribute(gemm_cp<3, false>,
                         cudaFuncAttributeMaxDynamicSharedMemorySize, GEMM_SMEM);

    // 0. split weights
    split_kernel<<<3 * DM * DM / 1024, 256>>>(w_qkv,  p_wqkv, 3 * DM * DM);
    split_kernel<<<DM * DM / 1024, 256>>>(w_proj, p_wprj, DM * DM);
    split_kernel<<<DFF * DM / 1024, 256>>>(w_ff1,  p_wff1, DFF * DM);
    split_kernel<<<DM * DFF / 1024, 256>>>(w_ff2,  p_wff2, DM * DFF);

    // 1. LN1 (split output)
    ln_kernel<<<MTOK, 256>>>(x, ln1_g, ln1_b, p_lns);
    // 2. QKV projection (fp32 out)
    gemm_cp<0, false><<<dim3(3 * DM / 128, MTOK / 128), 256, GEMM_SMEM>>>(
        p_lns, p_wqkv, nullptr, nullptr, p_qkv, nullptr, MTOK, 3 * DM, DM);
    // 3. causal flash attention on tensor cores (split output)
    attn_mma<<<dim3(BATCH * NHEADS, SEQ / 128), 256, ATT_SMEM>>>(p_qkv, p_atts);
    // 4. out projection + residual (fp32 out)
    gemm_cp<1, false><<<dim3(DM / 128, MTOK / 128), 256, GEMM_SMEM>>>(
        p_atts, p_wprj, nullptr, x, p_x1, nullptr, MTOK, DM, DM);
    // 5. LN2 (split output)
    ln_kernel<<<MTOK, 256>>>(p_x1, ln2_g, ln2_b, p_lns);
    // 6. FF1 + bias + exact GELU (split output)
    gemm_cp<2, true><<<dim3(DFF / 128, MTOK / 128), 256, GEMM_SMEM>>>(
        p_lns, p_wff1, b_ff1, nullptr, nullptr, p_ffs, MTOK, DFF, DM);
    // 7. FF2 + bias + residual -> out (fp32)
    gemm_cp<3, false><<<dim3(DM / 128, MTOK / 128), 256, GEMM_SMEM>>>(
        p_ffs, p_wff2, b_ff2, p_x1, out, nullptr, MTOK, DM, DFF);
}

// round 9
// speedup vs baseline: 3.6545x; 1.2496x over previous
#include <cuda_runtime.h>
#include <cuda_fp16.h>
#include <math.h>
#include <cstdint>

// Problem dims (fixed by reference)
#define BATCH   16
#define SEQ     512
#define DM      1024
#define NHEADS  16
#define HD      64
#define DFF     4096
#define MTOK    (BATCH*SEQ)          // 8192 rows

// ---------------- scratch (device globals; no allocations allowed) ---------
// "split format": per logical row of K fp32, K/32 blocks of 128B:
// [32 hi fp16 | 32 lo fp16]. Element (r,k): base + r*K*4 + (k>>5)*128 +
// (k&31)*2 (hi), +64 (lo). B-side operands only ever read the hi half.
__device__ uint8_t g_lns [MTOK * DM * 4];        // ln1/ln2 out (split)
__device__ float   g_qkv [MTOK * 3 * DM];        // qkv projections (fp32)
__device__ uint8_t g_atts[MTOK * DM * 4];        // attention out (split)
__device__ float   g_x1  [MTOK * DM];            // residual after attention
__device__ uint8_t g_ffs [MTOK * DFF * 4];       // ff1 activations (split)
__device__ uint8_t g_wqkv[3 * DM * DM * 4];      // split weights (hi used)
__device__ uint8_t g_wprj[DM * DM * 4];
__device__ uint8_t g_wff1[DFF * DM * 4];
__device__ uint8_t g_wff2[DM * DFF * 4];

#define SMEM_SWIZZLE_128B(byte_offset) \
    ((byte_offset) ^ (((byte_offset) >> 3) & 0x70))

__device__ __forceinline__ uint32_t smem_to_u32(const void* smem_ptr) {
    uint32_t addr;
    asm("{ .reg .u64 tmp; cvta.to.shared.u64 tmp, %1; cvt.u32.u64 %0, tmp; }"
        : "=r"(addr) : "l"(smem_ptr));
    return addr;
}

__device__ __forceinline__ void cp_async16(uint32_t dst, const void* src) {
    asm volatile("cp.async.ca.shared.global [%0], [%1], 16;"
                 :: "r"(dst), "l"(src));
}
#define CP_COMMIT() asm volatile("cp.async.commit_group;" ::: "memory")
#define CP_WAIT(n)  asm volatile("cp.async.wait_group %0;" :: "n"(n) : "memory")

__device__ __forceinline__ void ldmatrix_x4(uint32_t& r0, uint32_t& r1,
                                            uint32_t& r2, uint32_t& r3,
                                            uint32_t addr) {
    asm volatile("ldmatrix.sync.aligned.m8n8.x4.shared.b16 {%0,%1,%2,%3}, [%4];"
                 : "=r"(r0), "=r"(r1), "=r"(r2), "=r"(r3) : "r"(addr));
}

__device__ __forceinline__ void mma_f16(float* c, const uint32_t* a,
                                        const uint32_t* b) {
    asm volatile(
        "mma.sync.aligned.m16n8k16.row.col.f32.f16.f16.f32 "
        "{%0,%1,%2,%3}, {%4,%5,%6,%7}, {%8,%9}, {%0,%1,%2,%3};"
        : "+f"(c[0]), "+f"(c[1]), "+f"(c[2]), "+f"(c[3])
        : "r"(a[0]), "r"(a[1]), "r"(a[2]), "r"(a[3]), "r"(b[0]), "r"(b[1]));
}

__device__ __forceinline__ void split4_pack(const float4 v, uint2& hi, uint2& lo) {
    const __half hx = __float2half_rn(v.x);
    const __half hy = __float2half_rn(v.y);
    const __half hz = __float2half_rn(v.z);
    const __half hw = __float2half_rn(v.w);
    const __half lx = __float2half_rn(v.x - __half2float(hx));
    const __half ly = __float2half_rn(v.y - __half2float(hy));
    const __half lz = __float2half_rn(v.z - __half2float(hz));
    const __half lw = __float2half_rn(v.w - __half2float(hw));
    __half2 h0 = __halves2half2(hx, hy);
    __half2 h1 = __halves2half2(hz, hw);
    __half2 l0 = __halves2half2(lx, ly);
    __half2 l1 = __halves2half2(lz, lw);
    hi.x = *(uint32_t*)&h0; hi.y = *(uint32_t*)&h1;
    lo.x = *(uint32_t*)&l0; lo.y = *(uint32_t*)&l1;
}

__device__ __forceinline__ uint32_t pack2_hi(float a, float b) {
    __half2 h = __halves2half2(__float2half_rn(a), __float2half_rn(b));
    return *(uint32_t*)&h;
}
__device__ __forceinline__ uint32_t pack2_lo(float a, float b) {
    const __half ha = __float2half_rn(a), hb = __float2half_rn(b);
    __half2 l = __halves2half2(__float2half_rn(a - __half2float(ha)),
                               __float2half_rn(b - __half2float(hb)));
    return *(uint32_t*)&l;
}
__device__ __forceinline__ uint16_t h16(float x) {
    __half h = __float2half_rn(x); return *(uint16_t*)&h;
}

// ---------------------------------------------------------------------------
// Weight split kernel: writes hi halves only (weights are B-side operands).
// ---------------------------------------------------------------------------
__global__ void __launch_bounds__(256) split_kernel(const float* __restrict__ src,
                                                    uint8_t* __restrict__ dst,
                                                    int total)
{
    const int e0 = (blockIdx.x * 256 + threadIdx.x) * 4;
    if (e0 >= total) return;
    const float4 v = *(const float4*)(src + e0);
    __half2 h0 = __halves2half2(__float2half_rn(v.x), __float2half_rn(v.y));
    __half2 h1 = __halves2half2(__float2half_rn(v.z), __float2half_rn(v.w));
    uint2 hi; hi.x = *(uint32_t*)&h0; hi.y = *(uint32_t*)&h1;
    uint8_t* p = dst + (size_t)(e0 >> 5) * 128 + (e0 & 31) * 2;
    *(uint2*)(p) = hi;
}

// ---------------------------------------------------------------------------
// LayerNorm: one block per row; writes split format (hi+lo, A-side operand).
// ---------------------------------------------------------------------------
__global__ void __launch_bounds__(256) ln_kernel(const float* __restrict__ x,
                                                 const float* __restrict__ g,
                                                 const float* __restrict__ b,
                                                 uint8_t* __restrict__ y)
{
    const int row = blockIdx.x;
    const int tid = threadIdx.x;
    const float4 v = *(const float4*)(x + (size_t)row * DM + tid * 4);

    float s1 = v.x + v.y + v.z + v.w;
    float s2 = v.x*v.x + v.y*v.y + v.z*v.z + v.w*v.w;

    #pragma unroll
    for (int o = 16; o > 0; o >>= 1) {
        s1 += __shfl_xor_sync(0xffffffffu, s1, o);
        s2 += __shfl_xor_sync(0xffffffffu, s2, o);
    }
    __shared__ float r1[8], r2[8];
    if ((tid & 31) == 0) { r1[tid >> 5] = s1; r2[tid >> 5] = s2; }
    __syncthreads();
    float t1 = r1[tid & 7], t2 = r2[tid & 7];
    #pragma unroll
    for (int o = 4; o > 0; o >>= 1) {
        t1 += __shfl_xor_sync(0xffffffffu, t1, o);
        t2 += __shfl_xor_sync(0xffffffffu, t2, o);
    }
    const float mu  = t1 * (1.0f / DM);
    const float var = t2 * (1.0f / DM) - mu * mu;
    const float inv = rsqrtf(var + 1e-5f);

    const float4 gg = *(const float4*)(g + tid * 4);
    const float4 bb = *(const float4*)(b + tid * 4);
    float4 o4;
    o4.x = (v.x - mu) * inv * gg.x + bb.x;
    o4.y = (v.y - mu) * inv * gg.y + bb.y;
    o4.z = (v.z - mu) * inv * gg.z + bb.z;
    o4.w = (v.w - mu) * inv * gg.w + bb.w;

    uint2 hi, lo;
    split4_pack(o4, hi, lo);
    uint8_t* p = y + (size_t)row * DM * 4 + (tid >> 3) * 128 + (tid & 7) * 8;
    *(uint2*)(p)      = hi;
    *(uint2*)(p + 64) = lo;
}

// ---------------------------------------------------------------------------
// Tensor-core GEMM, fp16 2-pass split (A hi+lo, B hi only), 3-stage cp.async
// pipeline, 2 CTAs/SM. C[M,N] = A[M,K] @ B[N,K]^T (+epilogue).
// ---------------------------------------------------------------------------
#define NSTAGES 3
#define STAGE_BYTES 32768        // A 16KB + B 16KB (B lo half unwritten)
#define GEMM_SMEM (NSTAGES * STAGE_BYTES)

template<int EPI, bool OSPLIT>
__global__ void __launch_bounds__(256, 2) gemm_cp(const uint8_t* __restrict__ Aps,
                                                  const uint8_t* __restrict__ Bps,
                                                  const float* __restrict__ bias,
                                                  const float* __restrict__ res,
                                                  float* __restrict__ C,
                                                  uint8_t* __restrict__ Cs,
                                                  int M, int N, int K)
{
    extern __shared__ __align__(1024) char smem[];
    const uint32_t SU = smem_to_u32(smem);

    const int tid  = threadIdx.x;
    const int wid  = tid >> 5;
    const int lane = tid & 31;
    const int bm = blockIdx.y * 128;
    const int bn = blockIdx.x * 128;

    const int warpM = (wid >> 2) * 64;
    const int warpN = (wid & 3) * 32;

    const int aRow = ((lane >> 3) & 1) * 8 + (lane & 7);
    const int aCol = (lane >> 4) * 16;
    const int bRow = (lane >> 4) * 8 + (lane & 7);
    const int bCol = ((lane >> 3) & 1) * 16;

    const int g   = lane >> 2;
    const int tig = lane & 3;

    const size_t K4 = (size_t)K * 4;
    const uint8_t* Ab = Aps + (size_t)bm * K4;
    const uint8_t* Bb = Bps + (size_t)bn * K4;

    float acc[4][4][4];
    #pragma unroll
    for (int mt = 0; mt < 4; mt++)
        #pragma unroll
        for (int nt = 0; nt < 4; nt++)
            #pragma unroll
            for (int q = 0; q < 4; q++) acc[mt][nt][q] = 0.0f;

    const int NIT = K >> 5;

    auto issue_stage = [&](int it, int stage) {
        const uint32_t base = SU + stage * STAGE_BYTES;
        // A: full 16KB (hi+lo)
        #pragma unroll
        for (int i = 0; i < 4; i++) {
            const int c   = tid + i * 256;
            const int row = c >> 3;
            const int seg = (c & 7) * 16;
            cp_async16(base + SMEM_SWIZZLE_128B((uint32_t)(row * 128 + seg)),
                       Ab + (size_t)row * K4 + it * 128 + seg);
        }
        // B: hi halves only (8KB copied into 16KB region)
        #pragma unroll
        for (int i = 0; i < 2; i++) {
            const int c   = tid + i * 256;
            const int row = c >> 2;
            const int seg = (c & 3) * 16;    // 0..48 = hi half
            cp_async16(base + 16384 + SMEM_SWIZZLE_128B((uint32_t)(row * 128 + seg)),
                       Bb + (size_t)row * K4 + it * 128 + seg);
        }
    };

    #pragma unroll
    for (int s = 0; s < NSTAGES - 1; s++) {
        issue_stage(s, s);
        CP_COMMIT();
    }

    int ld_it = NSTAGES - 1;
    int ld_stage = NSTAGES - 1;
    int cm_stage = 0;

    for (int it = 0; it < NIT; ++it) {
        CP_WAIT(NSTAGES - 2);
        __syncthreads();

        if (ld_it < NIT) issue_stage(ld_it, ld_stage);
        CP_COMMIT();
        ld_it++;
        ld_stage = (ld_stage + 1 == NSTAGES) ? 0 : ld_stage + 1;

        const uint32_t AsU = SU + cm_stage * STAGE_BYTES;
        const uint32_t BsU = AsU + 16384;
        cm_stage = (cm_stage + 1 == NSTAGES) ? 0 : cm_stage + 1;

        #pragma unroll
        for (int s = 0; s < 2; s++) {
            const int kbH = s * 32;
            const int kbL = 64 + s * 32;

            uint32_t ahi[4][4], alo[4][4], bhi[2][4];
            #pragma unroll
            for (int mt = 0; mt < 4; mt++) {
                const int r = warpM + mt * 16 + aRow;
                ldmatrix_x4(ahi[mt][0], ahi[mt][1], ahi[mt][2], ahi[mt][3],
                    AsU + SMEM_SWIZZLE_128B((uint32_t)(r * 128 + kbH + aCol)));
                ldmatrix_x4(alo[mt][0], alo[mt][1], alo[mt][2], alo[mt][3],
                    AsU + SMEM_SWIZZLE_128B((uint32_t)(r * 128 + kbL + aCol)));
            }
            #pragma unroll
            for (int p = 0; p < 2; p++) {
                const int r = warpN + p * 16 + bRow;
                ldmatrix_x4(bhi[p][0], bhi[p][1], bhi[p][2], bhi[p][3],
                    BsU + SMEM_SWIZZLE_128B((uint32_t)(r * 128 + kbH + bCol)));
            }

            #pragma unroll
            for (int mt = 0; mt < 4; mt++)
                #pragma unroll
                for (int nt = 0; nt < 4; nt++) {
                    const uint32_t* bh = &bhi[nt >> 1][(nt & 1) * 2];
                    mma_f16(acc[mt][nt], ahi[mt], bh);
                    mma_f16(acc[mt][nt], alo[mt], bh);
                }
        }
        __syncthreads();
    }

    // ---- epilogue ----
    #pragma unroll
    for (int mt = 0; mt < 4; mt++) {
        #pragma unroll
        for (int nt = 0; nt < 4; nt++) {
            const int col = bn + warpN + nt * 8 + tig * 2;
            float v[4];
            #pragma unroll
            for (int q = 0; q < 4; q++) v[q] = acc[mt][nt][q];

            if (EPI == 2 || EPI == 3) {
                const float2 bv = *(const float2*)(bias + col);
                v[0] += bv.x; v[1] += bv.y; v[2] += bv.x; v[3] += bv.y;
            }
            if (EPI == 2) {
                #pragma unroll
                for (int q = 0; q < 4; q++)
                    v[q] = 0.5f * v[q] * (1.0f + erff(v[q] * 0.70710678118654752f));
            }
            const int row0 = bm + warpM + mt * 16 + g;
            const int row1 = row0 + 8;
            if (EPI == 1 || EPI == 3) {
                const float2 r0 = *(const float2*)(res + (size_t)row0 * N + col);
                const float2 r1 = *(const float2*)(res + (size_t)row1 * N + col);
                v[0] += r0.x; v[1] += r0.y; v[2] += r1.x; v[3] += r1.y;
            }
            if (OSPLIT) {
                uint8_t* p0 = Cs + (size_t)row0 * N * 4 + (col >> 5) * 128 + (col & 31) * 2;
                uint8_t* p1 = Cs + (size_t)row1 * N * 4 + (col >> 5) * 128 + (col & 31) * 2;
                *(uint32_t*)(p0)      = pack2_hi(v[0], v[1]);
                *(uint32_t*)(p0 + 64) = pack2_lo(v[0], v[1]);
                *(uint32_t*)(p1)      = pack2_hi(v[2], v[3]);
                *(uint32_t*)(p1 + 64) = pack2_lo(v[2], v[3]);
            } else {
                *(float2*)(C + (size_t)row0 * N + col) = make_float2(v[0], v[1]);
                *(float2*)(C + (size_t)row1 * N + col) = make_float2(v[2], v[3]);
            }
        }
    }
}

// ---------------------------------------------------------------------------
// Flash attention on tensor cores (fp16 2-pass split). Causal.
// One CTA = one (b,h) x 128 query rows. 8 warps, each warp 16 q-rows x full
// 64-key tile. Q split hi+lo; K and V hi only; V stored transposed.
// smem: Q 2 planes x 128 rows x 128B = 32KB @0      (hi+lo per plane)
//       K 2 planes x  64 rows x 128B = 16KB @32768  (hi used)
//       V 2 planes x  64 rows x 128B = 16KB @49152  (hi used)
// ---------------------------------------------------------------------------
#define ATT_SMEM 65536

__global__ void __launch_bounds__(256, 2) attn_mma(const float* __restrict__ qkv,
                                                   uint8_t* __restrict__ outs)
{
    extern __shared__ __align__(1024) uint8_t asmem[];
    const uint32_t SU = smem_to_u32(asmem);
    const uint32_t QU = SU;
    const uint32_t KU = SU + 32768;
    const uint32_t VU = SU + 49152;

    const int bh = blockIdx.x;          // 0..255
    const int qb = blockIdx.y;          // 0..3
    const int b  = bh >> 4;
    const int h  = bh & 15;

    const int tid  = threadIdx.x;
    const int wid  = tid >> 5;
    const int lane = tid & 31;
    const int g    = lane >> 2;
    const int tig  = lane & 3;

    const int aRow = ((lane >> 3) & 1) * 8 + (lane & 7);
    const int aCol = (lane >> 4) * 16;
    const int bRow = (lane >> 4) * 8 + (lane & 7);
    const int bCol = ((lane >> 3) & 1) * 16;

    const float* base = qkv + (size_t)(b * SEQ) * (3 * DM) + h * HD;

    // ---- load Q block (scaled by 1/8), split hi+lo into 2 d-planes ----
    #pragma unroll
    for (int i = 0; i < 8; i++) {
        const int idx = tid + i * 256;
        const int row = idx >> 4;
        const int d0  = (idx & 15) * 4;
        float4 v = *(const float4*)(base + (size_t)(qb * 128 + row) * (3 * DM) + d0);
        v.x *= 0.125f; v.y *= 0.125f; v.z *= 0.125f; v.w *= 0.125f;
        uint2 hi, lo;
        split4_pack(v, hi, lo);
        const uint32_t pl = (d0 >> 5) * 16384;
        const uint32_t c2 = (d0 & 31) * 2;
        *(uint2*)(asmem + (pl + SMEM_SWIZZLE_128B((uint32_t)(row * 128 + c2))))      = hi;
        *(uint2*)(asmem + (pl + SMEM_SWIZZLE_128B((uint32_t)(row * 128 + 64 + c2)))) = lo;
    }

    float m[2]  = {-1e30f, -1e30f};
    float l[2]  = {0.0f, 0.0f};
    float O[8][4];
    #pragma unroll
    for (int nt = 0; nt < 8; nt++)
        #pragma unroll
        for (int q = 0; q < 4; q++) O[nt][q] = 0.0f;

    const int kbmax = qb * 2 + 1;
    const int qrow0 = qb * 128 + wid * 16 + g;
    for (int kb = 0; kb <= kbmax; kb++) {
        __syncthreads();
        // ---- load K (hi only) and V^T (hi only) ----
        #pragma unroll
        for (int i = 0; i < 4; i++) {
            const int idx = tid + i * 256;
            const int key = idx >> 4;
            const int d0  = (idx & 15) * 4;
            const size_t grow = (size_t)(kb * 64 + key) * (3 * DM);
            // K hi
            {
                float4 v = *(const float4*)(base + DM + grow + d0);
                __half2 h0 = __halves2half2(__float2half_rn(v.x), __float2half_rn(v.y));
                __half2 h1 = __halves2half2(__float2half_rn(v.z), __float2half_rn(v.w));
                uint2 hi; hi.x = *(uint32_t*)&h0; hi.y = *(uint32_t*)&h1;
                const uint32_t pl = 32768 + (d0 >> 5) * 8192;
                const uint32_t c2 = (d0 & 31) * 2;
                *(uint2*)(asmem + (pl + SMEM_SWIZZLE_128B((uint32_t)(key * 128 + c2)))) = hi;
            }
            // V transposed hi: dest row = d, col = key
            {
                float4 v = *(const float4*)(base + 2 * DM + grow + d0);
                const uint32_t pl = 49152 + (key >> 5) * 8192;
                const uint32_t kc = (key & 31) * 2;
                const float vv[4] = {v.x, v.y, v.z, v.w};
                #pragma unroll
                for (int j = 0; j < 4; j++) {
                    const int d = d0 + j;
                    const uint32_t oh = pl + SMEM_SWIZZLE_128B((uint32_t)(d * 128 + kc));
                    *(uint16_t*)(asmem + oh) = h16(vv[j]);
                }
            }
        }
        __syncthreads();

        // ---- S = Q K^T (2-pass: Qhi.Kh + Qlo.Kh) ----
        float sacc[8][4];
        #pragma unroll
        for (int nt = 0; nt < 8; nt++)
            #pragma unroll
            for (int q = 0; q < 4; q++) sacc[nt][q] = 0.0f;

        #pragma unroll
        for (int s = 0; s < 4; s++) {
            const uint32_t qpl = QU + (s >> 1) * 16384;
            const int kbH = (s & 1) * 32;
            const int kbL = 64 + (s & 1) * 32;
            const int ra = wid * 16 + aRow;
            uint32_t ahi[4], alo[4];
            ldmatrix_x4(ahi[0], ahi[1], ahi[2], ahi[3],
                qpl + SMEM_SWIZZLE_128B((uint32_t)(ra * 128 + kbH + aCol)));
            ldmatrix_x4(alo[0], alo[1], alo[2], alo[3],
                qpl + SMEM_SWIZZLE_128B((uint32_t)(ra * 128 + kbL + aCol)));

            const uint32_t kpl = KU + (s >> 1) * 8192;
            #pragma unroll
            for (int p = 0; p < 4; p++) {
                const int r = p * 16 + bRow;
                uint32_t bhi[4];
                ldmatrix_x4(bhi[0], bhi[1], bhi[2], bhi[3],
                    kpl + SMEM_SWIZZLE_128B((uint32_t)(r * 128 + kbH + bCol)));
                #pragma unroll
                for (int u = 0; u < 2; u++) {
                    const int nt = p * 2 + u;
                    mma_f16(sacc[nt], ahi, &bhi[u * 2]);
                    mma_f16(sacc[nt], alo, &bhi[u * 2]);
                }
            }
        }

        // ---- causal mask ----
        if (kb >= qb * 2) {
            #pragma unroll
            for (int nt = 0; nt < 8; nt++) {
                const int col = kb * 64 + nt * 8 + tig * 2;
                if (col     > qrow0)     sacc[nt][0] = -10000.0f;
                if (col + 1 > qrow0)     sacc[nt][1] = -10000.0f;
                if (col     > qrow0 + 8) sacc[nt][2] = -10000.0f;
                if (col + 1 > qrow0 + 8) sacc[nt][3] = -10000.0f;
            }
        }

        // ---- online softmax (2 rows per thread) ----
        #pragma unroll
        for (int rh = 0; rh < 2; rh++) {
            const int q0 = rh * 2;
            float rm = -1e30f;
            #pragma unroll
            for (int nt = 0; nt < 8; nt++)
                rm = fmaxf(rm, fmaxf(sacc[nt][q0], sacc[nt][q0 + 1]));
            rm = fmaxf(rm, __shfl_xor_sync(0xffffffffu, rm, 1));
            rm = fmaxf(rm, __shfl_xor_sync(0xffffffffu, rm, 2));
            const float mn = fmaxf(m[rh], rm);
            const float alpha = __expf(m[rh] - mn);
            float rs = 0.0f;
            #pragma unroll
            for (int nt = 0; nt < 8; nt++) {
                sacc[nt][q0]     = __expf(sacc[nt][q0] - mn);
                sacc[nt][q0 + 1] = __expf(sacc[nt][q0 + 1] - mn);
                rs += sacc[nt][q0] + sacc[nt][q0 + 1];
            }
            rs += __shfl_xor_sync(0xffffffffu, rs, 1);
            rs += __shfl_xor_sync(0xffffffffu, rs, 2);
            l[rh] = l[rh] * alpha + rs;
            m[rh] = mn;
            #pragma unroll
            for (int nt = 0; nt < 8; nt++) {
                O[nt][q0]     *= alpha;
                O[nt][q0 + 1] *= alpha;
            }
        }

        // ---- O += P V  (P hi+lo from registers, V hi from smem) ----
        #pragma unroll
        for (int s = 0; s < 4; s++) {
            uint32_t phi[4], plo[4];
            phi[0] = pack2_hi(sacc[2*s][0],   sacc[2*s][1]);
            phi[1] = pack2_hi(sacc[2*s][2],   sacc[2*s][3]);
            phi[2] = pack2_hi(sacc[2*s+1][0], sacc[2*s+1][1]);
            phi[3] = pack2_hi(sacc[2*s+1][2], sacc[2*s+1][3]);
            plo[0] = pack2_lo(sacc[2*s][0],   sacc[2*s][1]);
            plo[1] = pack2_lo(sacc[2*s][2],   sacc[2*s][3]);
            plo[2] = pack2_lo(sacc[2*s+1][0], sacc[2*s+1][1]);
            plo[3] = pack2_lo(sacc[2*s+1][2], sacc[2*s+1][3]);

            const uint32_t vpl = VU + (s >> 1) * 8192;
            const int kbH = (s & 1) * 32;
            #pragma unroll
            for (int p = 0; p < 4; p++) {
                const int r = p * 16 + bRow;
                uint32_t vhi[4];
                ldmatrix_x4(vhi[0], vhi[1], vhi[2], vhi[3],
                    vpl + SMEM_SWIZZLE_128B((uint32_t)(r * 128 + kbH + bCol)));
                #pragma unroll
                for (int u = 0; u < 2; u++) {
                    const int nt = p * 2 + u;
                    mma_f16(O[nt], phi, &vhi[u * 2]);
                    mma_f16(O[nt], plo, &vhi[u * 2]);
                }
            }
        }
    }

    // ---- epilogue: normalize, write split-format attention output ----
    const float inv0 = 1.0f / l[0];
    const float inv1 = 1.0f / l[1];
    const size_t grow0 = (size_t)(b * SEQ + qb * 128 + wid * 16 + g);
    #pragma unroll
    for (int nt = 0; nt < 8; nt++) {
        const int col = h * HD + nt * 8 + tig * 2;
        uint8_t* p0 = outs + grow0 * DM * 4 + (col >> 5) * 128 + (col & 31) * 2;
        uint8_t* p1 = outs + (grow0 + 8) * DM * 4 + (col >> 5) * 128 + (col & 31) * 2;
        const float v0 = O[nt][0] * inv0, v1 = O[nt][1] * inv0;
        const float v2 = O[nt][2] * inv1, v3 = O[nt][3] * inv1;
        *(uint32_t*)(p0)      = pack2_hi(v0, v1);
        *(uint32_t*)(p0 + 64) = pack2_lo(v0, v1);
        *(uint32_t*)(p1)      = pack2_hi(v2, v3);
        *(uint32_t*)(p1 + 64) = pack2_lo(v2, v3);
    }
}

// ---------------------------------------------------------------------------
extern "C" void kernel_launch(void* const* d_in, const int* in_sizes, int n_in,
                              void* d_out, int out_size)
{
    const float* x      = (const float*)d_in[0];
    const float* w_qkv  = (const float*)d_in[1];
    const float* w_proj = (const float*)d_in[2];
    const float* w_ff1  = (const float*)d_in[3];
    const float* b_ff1  = (const float*)d_in[4];
    const float* w_ff2  = (const float*)d_in[5];
    const float* b_ff2  = (const float*)d_in[6];
    const float* ln1_g  = (const float*)d_in[7];
    const float* ln1_b  = (const float*)d_in[8];
    const float* ln2_g  = (const float*)d_in[9];
    const float* ln2_b  = (const float*)d_in[10];
    float* out = (float*)d_out;

    uint8_t *p_lns, *p_atts, *p_ffs, *p_wqkv, *p_wprj, *p_wff1, *p_wff2;
    float *p_qkv, *p_x1;
    cudaGetSymbolAddress((void**)&p_lns,  g_lns);
    cudaGetSymbolAddress((void**)&p_qkv,  g_qkv);
    cudaGetSymbolAddress((void**)&p_atts, g_atts);
    cudaGetSymbolAddress((void**)&p_x1,   g_x1);
    cudaGetSymbolAddress((void**)&p_ffs,  g_ffs);
    cudaGetSymbolAddress((void**)&p_wqkv, g_wqkv);
    cudaGetSymbolAddress((void**)&p_wprj, g_wprj);
    cudaGetSymbolAddress((void**)&p_wff1, g_wff1);
    cudaGetSymbolAddress((void**)&p_wff2, g_wff2);

    cudaFuncSetAttribute(attn_mma,
                         cudaFuncAttributeMaxDynamicSharedMemorySize, ATT_SMEM);
    cudaFuncSetAttribute(gemm_cp<0, false>,
                         cudaFuncAttributeMaxDynamicSharedMemorySize, GEMM_SMEM);
    cudaFuncSetAttribute(gemm_cp<1, false>,
                         cudaFuncAttributeMaxDynamicSharedMemorySize, GEMM_SMEM);
    cudaFuncSetAttribute(gemm_cp<2, true>,
                         cudaFuncAttributeMaxDynamicSharedMemorySize, GEMM_SMEM);
    cudaFuncSetAttribute(gemm_cp<3, false>,
                         cudaFuncAttributeMaxDynamicSharedMemorySize, GEMM_SMEM);

    // 0. split weights (hi only — B-side operands)
    split_kernel<<<3 * DM * DM / 1024, 256>>>(w_qkv,  p_wqkv, 3 * DM * DM);
    split_kernel<<<DM * DM / 1024, 256>>>(w_proj, p_wprj, DM * DM);
    split_kernel<<<DFF * DM / 1024, 256>>>(w_ff1,  p_wff1, DFF * DM);
    split_kernel<<<DM * DFF / 1024, 256>>>(w_ff2,  p_wff2, DM * DFF);

    // 1. LN1 (split output)
    ln_kernel<<<MTOK, 256>>>(x, ln1_g, ln1_b, p_lns);
    // 2. QKV projection (fp32 out)
    gemm_cp<0, false><<<dim3(3 * DM / 128, MTOK / 128), 256, GEMM_SMEM>>>(
        p_lns, p_wqkv, nullptr, nullptr, p_qkv, nullptr, MTOK, 3 * DM, DM);
    // 3. causal flash attention on tensor cores (split output)
    attn_mma<<<dim3(BATCH * NHEADS, SEQ / 128), 256, ATT_SMEM>>>(p_qkv, p_atts);
    // 4. out projection + residual (fp32 out)
    gemm_cp<1, false><<<dim3(DM / 128, MTOK / 128), 256, GEMM_SMEM>>>(
        p_atts, p_wprj, nullptr, x, p_x1, nullptr, MTOK, DM, DM);
    // 5. LN2 (split output)
    ln_kernel<<<MTOK, 256>>>(p_x1, ln2_g, ln2_b, p_lns);
    // 6. FF1 + bias + exact GELU (split output)
    gemm_cp<2, true><<<dim3(DFF / 128, MTOK / 128), 256, GEMM_SMEM>>>(
        p_lns, p_wff1, b_ff1, nullptr, nullptr, p_ffs, MTOK, DFF, DM);
    // 7. FF2 + bias + residual -> out (fp32)
    gemm_cp<3, false><<<dim3(DM / 128, MTOK / 128), 256, GEMM_SMEM>>>(
        p_ffs, p_wff2, b_ff2, p_x1, out, nullptr, MTOK, DM, DFF);
}

// round 10
// speedup vs baseline: 3.6804x; 1.0071x over previous
#include <cuda_runtime.h>
#include <cuda_fp16.h>
#include <math.h>
#include <cstdint>

// Problem dims (fixed by reference)
#define BATCH   16
#define SEQ     512
#define DM      1024
#define NHEADS  16
#define HD      64
#define DFF     4096
#define MTOK    (BATCH*SEQ)          // 8192 rows

// ---------------- scratch (device globals; no allocations allowed) ---------
// A-side "split format": per row of K fp32, K/32 blocks of 128B:
// [32 hi fp16 | 32 lo fp16]. Weights (B-side) are plain dense fp16 [N,K].
__device__ uint8_t  g_lns [MTOK * DM * 4];        // ln1/ln2 out (split)
__device__ float    g_qkv [MTOK * 3 * DM];        // qkv projections (fp32)
__device__ uint8_t  g_atts[MTOK * DM * 4];        // attention out (split)
__device__ float    g_x1  [MTOK * DM];            // residual after attention
__device__ uint8_t  g_ffs [MTOK * DFF * 4];       // ff1 activations (split)
__device__ uint16_t g_wqkv[3 * DM * DM];          // dense fp16 weights
__device__ uint16_t g_wprj[DM * DM];
__device__ uint16_t g_wff1[DFF * DM];
__device__ uint16_t g_wff2[DM * DFF];

#define SMEM_SWIZZLE_128B(byte_offset) \
    ((byte_offset) ^ (((byte_offset) >> 3) & 0x70))
#define SMEM_SWIZZLE_64B(byte_offset) \
    ((byte_offset) ^ (((byte_offset) >> 3) & 0x30))

__device__ __forceinline__ uint32_t smem_to_u32(const void* smem_ptr) {
    uint32_t addr;
    asm("{ .reg .u64 tmp; cvta.to.shared.u64 tmp, %1; cvt.u32.u64 %0, tmp; }"
        : "=r"(addr) : "l"(smem_ptr));
    return addr;
}

__device__ __forceinline__ void cp_async16(uint32_t dst, const void* src) {
    asm volatile("cp.async.ca.shared.global [%0], [%1], 16;"
                 :: "r"(dst), "l"(src));
}
#define CP_COMMIT() asm volatile("cp.async.commit_group;" ::: "memory")
#define CP_WAIT(n)  asm volatile("cp.async.wait_group %0;" :: "n"(n) : "memory")

__device__ __forceinline__ void ldmatrix_x4(uint32_t& r0, uint32_t& r1,
                                            uint32_t& r2, uint32_t& r3,
                                            uint32_t addr) {
    asm volatile("ldmatrix.sync.aligned.m8n8.x4.shared.b16 {%0,%1,%2,%3}, [%4];"
                 : "=r"(r0), "=r"(r1), "=r"(r2), "=r"(r3) : "r"(addr));
}

__device__ __forceinline__ void mma_f16(float* c, const uint32_t* a,
                                        const uint32_t* b) {
    asm volatile(
        "mma.sync.aligned.m16n8k16.row.col.f32.f16.f16.f32 "
        "{%0,%1,%2,%3}, {%4,%5,%6,%7}, {%8,%9}, {%0,%1,%2,%3};"
        : "+f"(c[0]), "+f"(c[1]), "+f"(c[2]), "+f"(c[3])
        : "r"(a[0]), "r"(a[1]), "r"(a[2]), "r"(a[3]), "r"(b[0]), "r"(b[1]));
}

__device__ __forceinline__ void split4_pack(const float4 v, uint2& hi, uint2& lo) {
    const __half hx = __float2half_rn(v.x);
    const __half hy = __float2half_rn(v.y);
    const __half hz = __float2half_rn(v.z);
    const __half hw = __float2half_rn(v.w);
    const __half lx = __float2half_rn(v.x - __half2float(hx));
    const __half ly = __float2half_rn(v.y - __half2float(hy));
    const __half lz = __float2half_rn(v.z - __half2float(hz));
    const __half lw = __float2half_rn(v.w - __half2float(hw));
    __half2 h0 = __halves2half2(hx, hy);
    __half2 h1 = __halves2half2(hz, hw);
    __half2 l0 = __halves2half2(lx, ly);
    __half2 l1 = __halves2half2(lz, lw);
    hi.x = *(uint32_t*)&h0; hi.y = *(uint32_t*)&h1;
    lo.x = *(uint32_t*)&l0; lo.y = *(uint32_t*)&l1;
}

__device__ __forceinline__ uint32_t pack2_hi(float a, float b) {
    __half2 h = __halves2half2(__float2half_rn(a), __float2half_rn(b));
    return *(uint32_t*)&h;
}
__device__ __forceinline__ uint32_t pack2_lo(float a, float b) {
    const __half ha = __float2half_rn(a), hb = __float2half_rn(b);
    __half2 l = __halves2half2(__float2half_rn(a - __half2float(ha)),
                               __float2half_rn(b - __half2float(hb)));
    return *(uint32_t*)&l;
}
__device__ __forceinline__ uint16_t h16(float x) {
    __half h = __float2half_rn(x); return *(uint16_t*)&h;
}

// ---------------------------------------------------------------------------
// Weight convert kernel: fp32 -> dense fp16.
// ---------------------------------------------------------------------------
__global__ void __launch_bounds__(256) split_kernel(const float* __restrict__ src,
                                                    uint16_t* __restrict__ dst,
                                                    int total)
{
    const int e0 = (blockIdx.x * 256 + threadIdx.x) * 4;
    if (e0 >= total) return;
    const float4 v = *(const float4*)(src + e0);
    __half2 h0 = __halves2half2(__float2half_rn(v.x), __float2half_rn(v.y));
    __half2 h1 = __halves2half2(__float2half_rn(v.z), __float2half_rn(v.w));
    uint2 hi; hi.x = *(uint32_t*)&h0; hi.y = *(uint32_t*)&h1;
    *(uint2*)(dst + e0) = hi;
}

// ---------------------------------------------------------------------------
// LayerNorm: one block per row; writes A-side split format.
// ---------------------------------------------------------------------------
__global__ void __launch_bounds__(256) ln_kernel(const float* __restrict__ x,
                                                 const float* __restrict__ g,
                                                 const float* __restrict__ b,
                                                 uint8_t* __restrict__ y)
{
    const int row = blockIdx.x;
    const int tid = threadIdx.x;
    const float4 v = *(const float4*)(x + (size_t)row * DM + tid * 4);

    float s1 = v.x + v.y + v.z + v.w;
    float s2 = v.x*v.x + v.y*v.y + v.z*v.z + v.w*v.w;

    #pragma unroll
    for (int o = 16; o > 0; o >>= 1) {
        s1 += __shfl_xor_sync(0xffffffffu, s1, o);
        s2 += __shfl_xor_sync(0xffffffffu, s2, o);
    }
    __shared__ float r1[8], r2[8];
    if ((tid & 31) == 0) { r1[tid >> 5] = s1; r2[tid >> 5] = s2; }
    __syncthreads();
    float t1 = r1[tid & 7], t2 = r2[tid & 7];
    #pragma unroll
    for (int o = 4; o > 0; o >>= 1) {
        t1 += __shfl_xor_sync(0xffffffffu, t1, o);
        t2 += __shfl_xor_sync(0xffffffffu, t2, o);
    }
    const float mu  = t1 * (1.0f / DM);
    const float var = t2 * (1.0f / DM) - mu * mu;
    const float inv = rsqrtf(var + 1e-5f);

    const float4 gg = *(const float4*)(g + tid * 4);
    const float4 bb = *(const float4*)(b + tid * 4);
    float4 o4;
    o4.x = (v.x - mu) * inv * gg.x + bb.x;
    o4.y = (v.y - mu) * inv * gg.y + bb.y;
    o4.z = (v.z - mu) * inv * gg.z + bb.z;
    o4.w = (v.w - mu) * inv * gg.w + bb.w;

    uint2 hi, lo;
    split4_pack(o4, hi, lo);
    uint8_t* p = y + (size_t)row * DM * 4 + (tid >> 3) * 128 + (tid & 7) * 8;
    *(uint2*)(p)      = hi;
    *(uint2*)(p + 64) = lo;
}

// ---------------------------------------------------------------------------
// Tensor-core GEMM: A split fp16 (hi+lo), B dense fp16; 2-pass A-split MMA.
// 4-stage cp.async pipeline (A 16KB @0, B 8KB 64B-row SW64 @16KB => 24KB/stage),
// 2 CTAs/SM, one barrier per K-tile. C[M,N] = A[M,K] @ B[N,K]^T (+epilogue).
// ---------------------------------------------------------------------------
#define NSTAGES 4
#define STAGE_BYTES 24576
#define GEMM_SMEM (NSTAGES * STAGE_BYTES)

template<int EPI, bool OSPLIT>
__global__ void __launch_bounds__(256, 2) gemm_cp(const uint8_t* __restrict__ Aps,
                                                  const uint8_t* __restrict__ Bps,
                                                  const float* __restrict__ bias,
                                                  const float* __restrict__ res,
                                                  float* __restrict__ C,
                                                  uint8_t* __restrict__ Cs,
                                                  int M, int N, int K)
{
    extern __shared__ __align__(1024) char smem[];
    const uint32_t SU = smem_to_u32(smem);

    const int tid  = threadIdx.x;
    const int wid  = tid >> 5;
    const int lane = tid & 31;
    const int bm = blockIdx.y * 128;
    const int bn = blockIdx.x * 128;

    const int warpM = (wid >> 2) * 64;
    const int warpN = (wid & 3) * 32;

    const int aRow = ((lane >> 3) & 1) * 8 + (lane & 7);
    const int aCol = (lane >> 4) * 16;
    const int bRow = (lane >> 4) * 8 + (lane & 7);
    const int bCol = ((lane >> 3) & 1) * 16;

    const int g   = lane >> 2;
    const int tig = lane & 3;

    const size_t K4 = (size_t)K * 4;     // A-side split row pitch (bytes)
    const size_t K2 = (size_t)K * 2;     // B-side dense fp16 row pitch (bytes)
    const uint8_t* Ab = Aps + (size_t)bm * K4;
    const uint8_t* Bb = Bps + (size_t)bn * K2;

    float acc[4][4][4];
    #pragma unroll
    for (int mt = 0; mt < 4; mt++)
        #pragma unroll
        for (int nt = 0; nt < 4; nt++)
            #pragma unroll
            for (int q = 0; q < 4; q++) acc[mt][nt][q] = 0.0f;

    const int NIT = K >> 5;

    auto issue_stage = [&](int it, int stage) {
        const uint32_t base = SU + stage * STAGE_BYTES;
        // A: 16KB (hi+lo), 128B rows, SW128
        #pragma unroll
        for (int i = 0; i < 4; i++) {
            const int c   = tid + i * 256;
            const int row = c >> 3;
            const int seg = (c & 7) * 16;
            cp_async16(base + SMEM_SWIZZLE_128B((uint32_t)(row * 128 + seg)),
                       Ab + (size_t)row * K4 + it * 128 + seg);
        }
        // B: 8KB dense hi, 64B rows, SW64
        #pragma unroll
        for (int i = 0; i < 2; i++) {
            const int c   = tid + i * 256;
            const int row = c >> 2;
            const int seg = (c & 3) * 16;
            cp_async16(base + 16384 + SMEM_SWIZZLE_64B((uint32_t)(row * 64 + seg)),
                       Bb + (size_t)row * K2 + it * 64 + seg);
        }
    };

    #pragma unroll
    for (int s = 0; s < NSTAGES - 1; s++) {
        issue_stage(s, s);
        CP_COMMIT();
    }

    int ld_it = NSTAGES - 1;
    int ld_stage = NSTAGES - 1;
    int cm_stage = 0;

    for (int it = 0; it < NIT; ++it) {
        CP_WAIT(NSTAGES - 2);
        __syncthreads();
        // After this barrier every warp has finished reading iteration it-1's
        // stage, which is exactly the stage being refilled below.
        if (ld_it < NIT) issue_stage(ld_it, ld_stage);
        CP_COMMIT();
        ld_it++;
        ld_stage = (ld_stage + 1 == NSTAGES) ? 0 : ld_stage + 1;

        const uint32_t AsU = SU + cm_stage * STAGE_BYTES;
        const uint32_t BsU = AsU + 16384;
        cm_stage = (cm_stage + 1 == NSTAGES) ? 0 : cm_stage + 1;

        #pragma unroll
        for (int s = 0; s < 2; s++) {
            const int kbH = s * 32;          // A hi bytes
            const int kbL = 64 + s * 32;     // A lo bytes
            const int kbB = s * 32;          // B bytes within 64B row

            uint32_t ahi[4][4], alo[4][4], bhi[2][4];
            #pragma unroll
            for (int mt = 0; mt < 4; mt++) {
                const int r = warpM + mt * 16 + aRow;
                ldmatrix_x4(ahi[mt][0], ahi[mt][1], ahi[mt][2], ahi[mt][3],
                    AsU + SMEM_SWIZZLE_128B((uint32_t)(r * 128 + kbH + aCol)));
                ldmatrix_x4(alo[mt][0], alo[mt][1], alo[mt][2], alo[mt][3],
                    AsU + SMEM_SWIZZLE_128B((uint32_t)(r * 128 + kbL + aCol)));
            }
            #pragma unroll
            for (int p = 0; p < 2; p++) {
                const int r = warpN + p * 16 + bRow;
                ldmatrix_x4(bhi[p][0], bhi[p][1], bhi[p][2], bhi[p][3],
                    BsU + SMEM_SWIZZLE_64B((uint32_t)(r * 64 + kbB + bCol)));
            }

            #pragma unroll
            for (int mt = 0; mt < 4; mt++)
                #pragma unroll
                for (int nt = 0; nt < 4; nt++) {
                    const uint32_t* bh = &bhi[nt >> 1][(nt & 1) * 2];
                    mma_f16(acc[mt][nt], ahi[mt], bh);
                    mma_f16(acc[mt][nt], alo[mt], bh);
                }
        }
    }

    // ---- epilogue ----
    #pragma unroll
    for (int mt = 0; mt < 4; mt++) {
        #pragma unroll
        for (int nt = 0; nt < 4; nt++) {
            const int col = bn + warpN + nt * 8 + tig * 2;
            float v[4];
            #pragma unroll
            for (int q = 0; q < 4; q++) v[q] = acc[mt][nt][q];

            if (EPI == 2 || EPI == 3) {
                const float2 bv = *(const float2*)(bias + col);
                v[0] += bv.x; v[1] += bv.y; v[2] += bv.x; v[3] += bv.y;
            }
            if (EPI == 2) {
                #pragma unroll
                for (int q = 0; q < 4; q++)
                    v[q] = 0.5f * v[q] * (1.0f + erff(v[q] * 0.70710678118654752f));
            }
            const int row0 = bm + warpM + mt * 16 + g;
            const int row1 = row0 + 8;
            if (EPI == 1 || EPI == 3) {
                const float2 r0 = *(const float2*)(res + (size_t)row0 * N + col);
                const float2 r1 = *(const float2*)(res + (size_t)row1 * N + col);
                v[0] += r0.x; v[1] += r0.y; v[2] += r1.x; v[3] += r1.y;
            }
            if (OSPLIT) {
                uint8_t* p0 = Cs + (size_t)row0 * N * 4 + (col >> 5) * 128 + (col & 31) * 2;
                uint8_t* p1 = Cs + (size_t)row1 * N * 4 + (col >> 5) * 128 + (col & 31) * 2;
                *(uint32_t*)(p0)      = pack2_hi(v[0], v[1]);
                *(uint32_t*)(p0 + 64) = pack2_lo(v[0], v[1]);
                *(uint32_t*)(p1)      = pack2_hi(v[2], v[3]);
                *(uint32_t*)(p1 + 64) = pack2_lo(v[2], v[3]);
            } else {
                *(float2*)(C + (size_t)row0 * N + col) = make_float2(v[0], v[1]);
                *(float2*)(C + (size_t)row1 * N + col) = make_float2(v[2], v[3]);
            }
        }
    }
}

// ---------------------------------------------------------------------------
// Flash attention on tensor cores (fp16 2-pass split). Causal. (As round 9.)
// ---------------------------------------------------------------------------
#define ATT_SMEM 65536

__global__ void __launch_bounds__(256, 2) attn_mma(const float* __restrict__ qkv,
                                                   uint8_t* __restrict__ outs)
{
    extern __shared__ __align__(1024) uint8_t asmem[];
    const uint32_t SU = smem_to_u32(asmem);
    const uint32_t QU = SU;
    const uint32_t KU = SU + 32768;
    const uint32_t VU = SU + 49152;

    const int bh = blockIdx.x;          // 0..255
    const int qb = blockIdx.y;          // 0..3
    const int b  = bh >> 4;
    const int h  = bh & 15;

    const int tid  = threadIdx.x;
    const int wid  = tid >> 5;
    const int lane = tid & 31;
    const int g    = lane >> 2;
    const int tig  = lane & 3;

    const int aRow = ((lane >> 3) & 1) * 8 + (lane & 7);
    const int aCol = (lane >> 4) * 16;
    const int bRow = (lane >> 4) * 8 + (lane & 7);
    const int bCol = ((lane >> 3) & 1) * 16;

    const float* base = qkv + (size_t)(b * SEQ) * (3 * DM) + h * HD;

    // ---- load Q block (scaled by 1/8), split hi+lo into 2 d-planes ----
    #pragma unroll
    for (int i = 0; i < 8; i++) {
        const int idx = tid + i * 256;
        const int row = idx >> 4;
        const int d0  = (idx & 15) * 4;
        float4 v = *(const float4*)(base + (size_t)(qb * 128 + row) * (3 * DM) + d0);
        v.x *= 0.125f; v.y *= 0.125f; v.z *= 0.125f; v.w *= 0.125f;
        uint2 hi, lo;
        split4_pack(v, hi, lo);
        const uint32_t pl = (d0 >> 5) * 16384;
        const uint32_t c2 = (d0 & 31) * 2;
        *(uint2*)(asmem + (pl + SMEM_SWIZZLE_128B((uint32_t)(row * 128 + c2))))      = hi;
        *(uint2*)(asmem + (pl + SMEM_SWIZZLE_128B((uint32_t)(row * 128 + 64 + c2)))) = lo;
    }

    float m[2]  = {-1e30f, -1e30f};
    float l[2]  = {0.0f, 0.0f};
    float O[8][4];
    #pragma unroll
    for (int nt = 0; nt < 8; nt++)
        #pragma unroll
        for (int q = 0; q < 4; q++) O[nt][q] = 0.0f;

    const int kbmax = qb * 2 + 1;
    const int qrow0 = qb * 128 + wid * 16 + g;
    for (int kb = 0; kb <= kbmax; kb++) {
        __syncthreads();
        // ---- load K (hi only) and V^T (hi only) ----
        #pragma unroll
        for (int i = 0; i < 4; i++) {
            const int idx = tid + i * 256;
            const int key = idx >> 4;
            const int d0  = (idx & 15) * 4;
            const size_t grow = (size_t)(kb * 64 + key) * (3 * DM);
            // K hi
            {
                float4 v = *(const float4*)(base + DM + grow + d0);
                __half2 h0 = __halves2half2(__float2half_rn(v.x), __float2half_rn(v.y));
                __half2 h1 = __halves2half2(__float2half_rn(v.z), __float2half_rn(v.w));
                uint2 hi; hi.x = *(uint32_t*)&h0; hi.y = *(uint32_t*)&h1;
                const uint32_t pl = 32768 + (d0 >> 5) * 8192;
                const uint32_t c2 = (d0 & 31) * 2;
                *(uint2*)(asmem + (pl + SMEM_SWIZZLE_128B((uint32_t)(key * 128 + c2)))) = hi;
            }
            // V transposed hi: dest row = d, col = key
            {
                float4 v = *(const float4*)(base + 2 * DM + grow + d0);
                const uint32_t pl = 49152 + (key >> 5) * 8192;
                const uint32_t kc = (key & 31) * 2;
                const float vv[4] = {v.x, v.y, v.z, v.w};
                #pragma unroll
                for (int j = 0; j < 4; j++) {
                    const int d = d0 + j;
                    const uint32_t oh = pl + SMEM_SWIZZLE_128B((uint32_t)(d * 128 + kc));
                    *(uint16_t*)(asmem + oh) = h16(vv[j]);
                }
            }
        }
        __syncthreads();

        // ---- S = Q K^T (2-pass) ----
        float sacc[8][4];
        #pragma unroll
        for (int nt = 0; nt < 8; nt++)
            #pragma unroll
            for (int q = 0; q < 4; q++) sacc[nt][q] = 0.0f;

        #pragma unroll
        for (int s = 0; s < 4; s++) {
            const uint32_t qpl = QU + (s >> 1) * 16384;
            const int kbH = (s & 1) * 32;
            const int kbL = 64 + (s & 1) * 32;
            const int ra = wid * 16 + aRow;
            uint32_t ahi[4], alo[4];
            ldmatrix_x4(ahi[0], ahi[1], ahi[2], ahi[3],
                qpl + SMEM_SWIZZLE_128B((uint32_t)(ra * 128 + kbH + aCol)));
            ldmatrix_x4(alo[0], alo[1], alo[2], alo[3],
                qpl + SMEM_SWIZZLE_128B((uint32_t)(ra * 128 + kbL + aCol)));

            const uint32_t kpl = KU + (s >> 1) * 8192;
            #pragma unroll
            for (int p = 0; p < 4; p++) {
                const int r = p * 16 + bRow;
                uint32_t bhi[4];
                ldmatrix_x4(bhi[0], bhi[1], bhi[2], bhi[3],
                    kpl + SMEM_SWIZZLE_128B((uint32_t)(r * 128 + kbH + bCol)));
                #pragma unroll
                for (int u = 0; u < 2; u++) {
                    const int nt = p * 2 + u;
                    mma_f16(sacc[nt], ahi, &bhi[u * 2]);
                    mma_f16(sacc[nt], alo, &bhi[u * 2]);
                }
            }
        }

        // ---- causal mask ----
        if (kb >= qb * 2) {
            #pragma unroll
            for (int nt = 0; nt < 8; nt++) {
                const int col = kb * 64 + nt * 8 + tig * 2;
                if (col     > qrow0)     sacc[nt][0] = -10000.0f;
                if (col + 1 > qrow0)     sacc[nt][1] = -10000.0f;
                if (col     > qrow0 + 8) sacc[nt][2] = -10000.0f;
                if (col + 1 > qrow0 + 8) sacc[nt][3] = -10000.0f;
            }
        }

        // ---- online softmax (2 rows per thread) ----
        #pragma unroll
        for (int rh = 0; rh < 2; rh++) {
            const int q0 = rh * 2;
            float rm = -1e30f;
            #pragma unroll
            for (int nt = 0; nt < 8; nt++)
                rm = fmaxf(rm, fmaxf(sacc[nt][q0], sacc[nt][q0 + 1]));
            rm = fmaxf(rm, __shfl_xor_sync(0xffffffffu, rm, 1));
            rm = fmaxf(rm, __shfl_xor_sync(0xffffffffu, rm, 2));
            const float mn = fmaxf(m[rh], rm);
            const float alpha = __expf(m[rh] - mn);
            float rs = 0.0f;
            #pragma unroll
            for (int nt = 0; nt < 8; nt++) {
                sacc[nt][q0]     = __expf(sacc[nt][q0] - mn);
                sacc[nt][q0 + 1] = __expf(sacc[nt][q0 + 1] - mn);
                rs += sacc[nt][q0] + sacc[nt][q0 + 1];
            }
            rs += __shfl_xor_sync(0xffffffffu, rs, 1);
            rs += __shfl_xor_sync(0xffffffffu, rs, 2);
            l[rh] = l[rh] * alpha + rs;
            m[rh] = mn;
            #pragma unroll
            for (int nt = 0; nt < 8; nt++) {
                O[nt][q0]     *= alpha;
                O[nt][q0 + 1] *= alpha;
            }
        }

        // ---- O += P V ----
        #pragma unroll
        for (int s = 0; s < 4; s++) {
            uint32_t phi[4], plo[4];
            phi[0] = pack2_hi(sacc[2*s][0],   sacc[2*s][1]);
            phi[1] = pack2_hi(sacc[2*s][2],   sacc[2*s][3]);
            phi[2] = pack2_hi(sacc[2*s+1][0], sacc[2*s+1][1]);
            phi[3] = pack2_hi(sacc[2*s+1][2], sacc[2*s+1][3]);
            plo[0] = pack2_lo(sacc[2*s][0],   sacc[2*s][1]);
            plo[1] = pack2_lo(sacc[2*s][2],   sacc[2*s][3]);
            plo[2] = pack2_lo(sacc[2*s+1][0], sacc[2*s+1][1]);
            plo[3] = pack2_lo(sacc[2*s+1][2], sacc[2*s+1][3]);

            const uint32_t vpl = VU + (s >> 1) * 8192;
            const int kbH = (s & 1) * 32;
            #pragma unroll
            for (int p = 0; p < 4; p++) {
                const int r = p * 16 + bRow;
                uint32_t vhi[4];
                ldmatrix_x4(vhi[0], vhi[1], vhi[2], vhi[3],
                    vpl + SMEM_SWIZZLE_128B((uint32_t)(r * 128 + kbH + bCol)));
                #pragma unroll
                for (int u = 0; u < 2; u++) {
                    const int nt = p * 2 + u;
                    mma_f16(O[nt], phi, &vhi[u * 2]);
                    mma_f16(O[nt], plo, &vhi[u * 2]);
                }
            }
        }
    }

    // ---- epilogue: normalize, write split-format attention output ----
    const float inv0 = 1.0f / l[0];
    const float inv1 = 1.0f / l[1];
    const size_t grow0 = (size_t)(b * SEQ + qb * 128 + wid * 16 + g);
    #pragma unroll
    for (int nt = 0; nt < 8; nt++) {
        const int col = h * HD + nt * 8 + tig * 2;
        uint8_t* p0 = outs + grow0 * DM * 4 + (col >> 5) * 128 + (col & 31) * 2;
        uint8_t* p1 = outs + (grow0 + 8) * DM * 4 + (col >> 5) * 128 + (col & 31) * 2;
        const float v0 = O[nt][0] * inv0, v1 = O[nt][1] * inv0;
        const float v2 = O[nt][2] * inv1, v3 = O[nt][3] * inv1;
        *(uint32_t*)(p0)      = pack2_hi(v0, v1);
        *(uint32_t*)(p0 + 64) = pack2_lo(v0, v1);
        *(uint32_t*)(p1)      = pack2_hi(v2, v3);
        *(uint32_t*)(p1 + 64) = pack2_lo(v2, v3);
    }
}

// ---------------------------------------------------------------------------
extern "C" void kernel_launch(void* const* d_in, const int* in_sizes, int n_in,
                              void* d_out, int out_size)
{
    const float* x      = (const float*)d_in[0];
    const float* w_qkv  = (const float*)d_in[1];
    const float* w_proj = (const float*)d_in[2];
    const float* w_ff1  = (const float*)d_in[3];
    const float* b_ff1  = (const float*)d_in[4];
    const float* w_ff2  = (const float*)d_in[5];
    const float* b_ff2  = (const float*)d_in[6];
    const float* ln1_g  = (const float*)d_in[7];
    const float* ln1_b  = (const float*)d_in[8];
    const float* ln2_g  = (const float*)d_in[9];
    const float* ln2_b  = (const float*)d_in[10];
    float* out = (float*)d_out;

    uint8_t *p_lns, *p_atts, *p_ffs;
    uint16_t *p_wqkv, *p_wprj, *p_wff1, *p_wff2;
    float *p_qkv, *p_x1;
    cudaGetSymbolAddress((void**)&p_lns,  g_lns);
    cudaGetSymbolAddress((void**)&p_qkv,  g_qkv);
    cudaGetSymbolAddress((void**)&p_atts, g_atts);
    cudaGetSymbolAddress((void**)&p_x1,   g_x1);
    cudaGetSymbolAddress((void**)&p_ffs,  g_ffs);
    cudaGetSymbolAddress((void**)&p_wqkv, g_wqkv);
    cudaGetSymbolAddress((void**)&p_wprj, g_wprj);
    cudaGetSymbolAddress((void**)&p_wff1, g_wff1);
    cudaGetSymbolAddress((void**)&p_wff2, g_wff2);

    cudaFuncSetAttribute(attn_mma,
                         cudaFuncAttributeMaxDynamicSharedMemorySize, ATT_SMEM);
    cudaFuncSetAttribute(gemm_cp<0, false>,
                         cudaFuncAttributeMaxDynamicSharedMemorySize, GEMM_SMEM);
    cudaFuncSetAttribute(gemm_cp<1, false>,
                         cudaFuncAttributeMaxDynamicSharedMemorySize, GEMM_SMEM);
    cudaFuncSetAttribute(gemm_cp<2, true>,
                         cudaFuncAttributeMaxDynamicSharedMemorySize, GEMM_SMEM);
    cudaFuncSetAttribute(gemm_cp<3, false>,
                         cudaFuncAttributeMaxDynamicSharedMemorySize, GEMM_SMEM);

    // 0. convert weights to dense fp16
    split_kernel<<<3 * DM * DM / 1024, 256>>>(w_qkv,  p_wqkv, 3 * DM * DM);
    split_kernel<<<DM * DM / 1024, 256>>>(w_proj, p_wprj, DM * DM);
    split_kernel<<<DFF * DM / 1024, 256>>>(w_ff1,  p_wff1, DFF * DM);
    split_kernel<<<DM * DFF / 1024, 256>>>(w_ff2,  p_wff2, DM * DFF);

    // 1. LN1 (split output)
    ln_kernel<<<MTOK, 256>>>(x, ln1_g, ln1_b, p_lns);
    // 2. QKV projection (fp32 out)
    gemm_cp<0, false><<<dim3(3 * DM / 128, MTOK / 128), 256, GEMM_SMEM>>>(
        p_lns, (const uint8_t*)p_wqkv, nullptr, nullptr, p_qkv, nullptr,
        MTOK, 3 * DM, DM);
    // 3. causal flash attention on tensor cores (split output)
    attn_mma<<<dim3(BATCH * NHEADS, SEQ / 128), 256, ATT_SMEM>>>(p_qkv, p_atts);
    // 4. out projection + residual (fp32 out)
    gemm_cp<1, false><<<dim3(DM / 128, MTOK / 128), 256, GEMM_SMEM>>>(
        p_atts, (const uint8_t*)p_wprj, nullptr, x, p_x1, nullptr,
        MTOK, DM, DM);
    // 5. LN2 (split output)
    ln_kernel<<<MTOK, 256>>>(p_x1, ln2_g, ln2_b, p_lns);
    // 6. FF1 + bias + exact GELU (split output)
    gemm_cp<2, true><<<dim3(DFF / 128, MTOK / 128), 256, GEMM_SMEM>>>(
        p_lns, (const uint8_t*)p_wff1, b_ff1, nullptr, nullptr, p_ffs,
        MTOK, DFF, DM);
    // 7. FF2 + bias + residual -> out (fp32)
    gemm_cp<3, false><<<dim3(DM / 128, MTOK / 128), 256, GEMM_SMEM>>>(
        p_ffs, (const uint8_t*)p_wff2, b_ff2, p_x1, out, nullptr,
        MTOK, DM, DFF);
}

// round 14
// speedup vs baseline: 3.7387x; 1.0158x over previous
#include <cuda_runtime.h>
#include <cuda_fp16.h>
#include <math.h>
#include <cstdint>

// Problem dims (fixed by reference)
#define BATCH   16
#define SEQ     512
#define DM      1024
#define NHEADS  16
#define HD      64
#define DFF     4096
#define MTOK    (BATCH*SEQ)          // 8192 rows

// ---------------- scratch (device globals; no allocations allowed) ---------
// All GEMM operands are dense fp16 [rows, K], K-contiguous.
__device__ uint16_t g_lns [MTOK * DM];            // ln1/ln2 out (fp16)
__device__ float    g_qkv [MTOK * 3 * DM];        // qkv projections (fp32)
__device__ uint16_t g_atts[MTOK * DM];            // attention out (fp16)
__device__ float    g_x1  [MTOK * DM];            // residual after attention
__device__ uint16_t g_ffs [MTOK * DFF];           // ff1 activations (fp16)
__device__ uint16_t g_wqkv[3 * DM * DM];          // fp16 weights
__device__ uint16_t g_wprj[DM * DM];
__device__ uint16_t g_wff1[DFF * DM];
__device__ uint16_t g_wff2[DM * DFF];

#define SMEM_SWIZZLE_128B(byte_offset) \
    ((byte_offset) ^ (((byte_offset) >> 3) & 0x70))
#define SMEM_SWIZZLE_64B(byte_offset) \
    ((byte_offset) ^ (((byte_offset) >> 3) & 0x30))

__device__ __forceinline__ uint32_t smem_to_u32(const void* smem_ptr) {
    uint32_t addr;
    asm("{ .reg .u64 tmp; cvta.to.shared.u64 tmp, %1; cvt.u32.u64 %0, tmp; }"
        : "=r"(addr) : "l"(smem_ptr));
    return addr;
}

__device__ __forceinline__ void cp_async16(uint32_t dst, const void* src) {
    asm volatile("cp.async.ca.shared.global [%0], [%1], 16;"
                 :: "r"(dst), "l"(src));
}
#define CP_COMMIT() asm volatile("cp.async.commit_group;" ::: "memory")
#define CP_WAIT(n)  asm volatile("cp.async.wait_group %0;" :: "n"(n) : "memory")

__device__ __forceinline__ void ldmatrix_x4(uint32_t& r0, uint32_t& r1,
                                            uint32_t& r2, uint32_t& r3,
                                            uint32_t addr) {
    asm volatile("ldmatrix.sync.aligned.m8n8.x4.shared.b16 {%0,%1,%2,%3}, [%4];"
                 : "=r"(r0), "=r"(r1), "=r"(r2), "=r"(r3) : "r"(addr));
}

__device__ __forceinline__ void mma_f16(float* c, const uint32_t* a,
                                        const uint32_t* b) {
    asm volatile(
        "mma.sync.aligned.m16n8k16.row.col.f32.f16.f16.f32 "
        "{%0,%1,%2,%3}, {%4,%5,%6,%7}, {%8,%9}, {%0,%1,%2,%3};"
        : "+f"(c[0]), "+f"(c[1]), "+f"(c[2]), "+f"(c[3])
        : "r"(a[0]), "r"(a[1]), "r"(a[2]), "r"(a[3]), "r"(b[0]), "r"(b[1]));
}

__device__ __forceinline__ void split4_pack(const float4 v, uint2& hi, uint2& lo) {
    const __half hx = __float2half_rn(v.x);
    const __half hy = __float2half_rn(v.y);
    const __half hz = __float2half_rn(v.z);
    const __half hw = __float2half_rn(v.w);
    const __half lx = __float2half_rn(v.x - __half2float(hx));
    const __half ly = __float2half_rn(v.y - __half2float(hy));
    const __half lz = __float2half_rn(v.z - __half2float(hz));
    const __half lw = __float2half_rn(v.w - __half2float(hw));
    __half2 h0 = __halves2half2(hx, hy);
    __half2 h1 = __halves2half2(hz, hw);
    __half2 l0 = __halves2half2(lx, ly);
    __half2 l1 = __halves2half2(lz, lw);
    hi.x = *(uint32_t*)&h0; hi.y = *(uint32_t*)&h1;
    lo.x = *(uint32_t*)&l0; lo.y = *(uint32_t*)&l1;
}

__device__ __forceinline__ uint32_t pack2_hi(float a, float b) {
    __half2 h = __halves2half2(__float2half_rn(a), __float2half_rn(b));
    return *(uint32_t*)&h;
}
__device__ __forceinline__ uint32_t pack2_lo(float a, float b) {
    const __half ha = __float2half_rn(a), hb = __float2half_rn(b);
    __half2 l = __halves2half2(__float2half_rn(a - __half2float(ha)),
                               __float2half_rn(b - __half2float(hb)));
    return *(uint32_t*)&l;
}
__device__ __forceinline__ uint16_t h16(float x) {
    __half h = __float2half_rn(x); return *(uint16_t*)&h;
}

// ---------------------------------------------------------------------------
// Weight convert kernel: fp32 -> dense fp16.
// ---------------------------------------------------------------------------
__global__ void __launch_bounds__(256) split_kernel(const float* __restrict__ src,
                                                    uint16_t* __restrict__ dst,
                                                    int total)
{
    const int e0 = (blockIdx.x * 256 + threadIdx.x) * 4;
    if (e0 >= total) return;
    const float4 v = *(const float4*)(src + e0);
    __half2 h0 = __halves2half2(__float2half_rn(v.x), __float2half_rn(v.y));
    __half2 h1 = __halves2half2(__float2half_rn(v.z), __float2half_rn(v.w));
    uint2 hi; hi.x = *(uint32_t*)&h0; hi.y = *(uint32_t*)&h1;
    *(uint2*)(dst + e0) = hi;
}

// ---------------------------------------------------------------------------
// LayerNorm: one block per row; writes dense fp16.
// ---------------------------------------------------------------------------
__global__ void __launch_bounds__(256) ln_kernel(const float* __restrict__ x,
                                                 const float* __restrict__ g,
                                                 const float* __restrict__ b,
                                                 uint16_t* __restrict__ y)
{
    const int row = blockIdx.x;
    const int tid = threadIdx.x;
    const float4 v = *(const float4*)(x + (size_t)row * DM + tid * 4);

    float s1 = v.x + v.y + v.z + v.w;
    float s2 = v.x*v.x + v.y*v.y + v.z*v.z + v.w*v.w;

    #pragma unroll
    for (int o = 16; o > 0; o >>= 1) {
        s1 += __shfl_xor_sync(0xffffffffu, s1, o);
        s2 += __shfl_xor_sync(0xffffffffu, s2, o);
    }
    __shared__ float r1[8], r2[8];
    if ((tid & 31) == 0) { r1[tid >> 5] = s1; r2[tid >> 5] = s2; }
    __syncthreads();
    float t1 = r1[tid & 7], t2 = r2[tid & 7];
    #pragma unroll
    for (int o = 4; o > 0; o >>= 1) {
        t1 += __shfl_xor_sync(0xffffffffu, t1, o);
        t2 += __shfl_xor_sync(0xffffffffu, t2, o);
    }
    const float mu  = t1 * (1.0f / DM);
    const float var = t2 * (1.0f / DM) - mu * mu;
    const float inv = rsqrtf(var + 1e-5f);

    const float4 gg = *(const float4*)(g + tid * 4);
    const float4 bb = *(const float4*)(b + tid * 4);
    float4 o4;
    o4.x = (v.x - mu) * inv * gg.x + bb.x;
    o4.y = (v.y - mu) * inv * gg.y + bb.y;
    o4.z = (v.z - mu) * inv * gg.z + bb.z;
    o4.w = (v.w - mu) * inv * gg.w + bb.w;

    __half2 h0 = __halves2half2(__float2half_rn(o4.x), __float2half_rn(o4.y));
    __half2 h1 = __halves2half2(__float2half_rn(o4.z), __float2half_rn(o4.w));
    uint2 hi; hi.x = *(uint32_t*)&h0; hi.y = *(uint32_t*)&h1;
    *(uint2*)(y + (size_t)row * DM + tid * 4) = hi;
}

// ---------------------------------------------------------------------------
// Tensor-core GEMM: dense fp16 A and B (single pass). 6-stage cp.async
// pipeline (A 8KB @0, B 8KB @8192, both 64B rows SW64 => 16KB/stage),
// 2 CTAs/SM. C[M,N] = A[M,K] @ B[N,K]^T (+epilogue).
// EPI: 0 none, 1 +res, 2 +bias,gelu, 3 +bias,+res.  OF16: write fp16 Cs.
// ---------------------------------------------------------------------------
#define NSTAGES 6
#define STAGE_BYTES 16384
#define GEMM_SMEM (NSTAGES * STAGE_BYTES)

template<int EPI, bool OF16>
__global__ void __launch_bounds__(256, 2) gemm_cp(const uint16_t* __restrict__ Ah,
                                                  const uint16_t* __restrict__ Bh,
                                                  const float* __restrict__ bias,
                                                  const float* __restrict__ res,
                                                  float* __restrict__ C,
                                                  uint16_t* __restrict__ Cs,
                                                  int M, int N, int K)
{
    extern __shared__ __align__(1024) char smem[];
    const uint32_t SU = smem_to_u32(smem);

    const int tid  = threadIdx.x;
    const int wid  = tid >> 5;
    const int lane = tid & 31;
    const int bm = blockIdx.y * 128;
    const int bn = blockIdx.x * 128;

    const int warpM = (wid >> 2) * 64;
    const int warpN = (wid & 3) * 32;

    const int aRow = ((lane >> 3) & 1) * 8 + (lane & 7);
    const int aCol = (lane >> 4) * 16;
    const int bRow = (lane >> 4) * 8 + (lane & 7);
    const int bCol = ((lane >> 3) & 1) * 16;

    const int g   = lane >> 2;
    const int tig = lane & 3;

    const size_t K2 = (size_t)K * 2;     // fp16 row pitch (bytes)
    const uint8_t* Ab = (const uint8_t*)Ah + (size_t)bm * K2;
    const uint8_t* Bb = (const uint8_t*)Bh + (size_t)bn * K2;

    float acc[4][4][4];
    #pragma unroll
    for (int mt = 0; mt < 4; mt++)
        #pragma unroll
        for (int nt = 0; nt < 4; nt++)
            #pragma unroll
            for (int q = 0; q < 4; q++) acc[mt][nt][q] = 0.0f;

    const int NIT = K >> 5;

    auto issue_stage = [&](int it, int stage) {
        const uint32_t base = SU + stage * STAGE_BYTES;
        #pragma unroll
        for (int i = 0; i < 2; i++) {
            const int c   = tid + i * 256;
            const int row = c >> 2;
            const int seg = (c & 3) * 16;
            const uint32_t soff = SMEM_SWIZZLE_64B((uint32_t)(row * 64 + seg));
            cp_async16(base + soff,        Ab + (size_t)row * K2 + it * 64 + seg);
            cp_async16(base + 8192 + soff, Bb + (size_t)row * K2 + it * 64 + seg);
        }
    };

    #pragma unroll
    for (int s = 0; s < NSTAGES - 1; s++) {
        issue_stage(s, s);
        CP_COMMIT();
    }

    int ld_it = NSTAGES - 1;
    int ld_stage = NSTAGES - 1;
    int cm_stage = 0;

    for (int it = 0; it < NIT; ++it) {
        CP_WAIT(NSTAGES - 2);
        __syncthreads();
        // The barrier also proves every warp finished reading the stage
        // being refilled below (it was consumed in iteration it-1).
        if (ld_it < NIT) issue_stage(ld_it, ld_stage);
        CP_COMMIT();
        ld_it++;
        ld_stage = (ld_stage + 1 == NSTAGES) ? 0 : ld_stage + 1;

        const uint32_t AsU = SU + cm_stage * STAGE_BYTES;
        const uint32_t BsU = AsU + 8192;
        cm_stage = (cm_stage + 1 == NSTAGES) ? 0 : cm_stage + 1;

        #pragma unroll
        for (int s = 0; s < 2; s++) {
            const int kb = s * 32;

            uint32_t af[4][4], bf[2][4];
            #pragma unroll
            for (int mt = 0; mt < 4; mt++) {
                const int r = warpM + mt * 16 + aRow;
                ldmatrix_x4(af[mt][0], af[mt][1], af[mt][2], af[mt][3],
                    AsU + SMEM_SWIZZLE_64B((uint32_t)(r * 64 + kb + aCol)));
            }
            #pragma unroll
            for (int p = 0; p < 2; p++) {
                const int r = warpN + p * 16 + bRow;
                ldmatrix_x4(bf[p][0], bf[p][1], bf[p][2], bf[p][3],
                    BsU + SMEM_SWIZZLE_64B((uint32_t)(r * 64 + kb + bCol)));
            }

            #pragma unroll
            for (int mt = 0; mt < 4; mt++)
                #pragma unroll
                for (int nt = 0; nt < 4; nt++)
                    mma_f16(acc[mt][nt], af[mt], &bf[nt >> 1][(nt & 1) * 2]);
        }
    }

    // ---- epilogue ----
    #pragma unroll
    for (int mt = 0; mt < 4; mt++) {
        #pragma unroll
        for (int nt = 0; nt < 4; nt++) {
            const int col = bn + warpN + nt * 8 + tig * 2;
            float v[4];
            #pragma unroll
            for (int q = 0; q < 4; q++) v[q] = acc[mt][nt][q];

            if (EPI == 2 || EPI == 3) {
                const float2 bv = *(const float2*)(bias + col);
                v[0] += bv.x; v[1] += bv.y; v[2] += bv.x; v[3] += bv.y;
            }
            if (EPI == 2) {
                #pragma unroll
                for (int q = 0; q < 4; q++)
                    v[q] = 0.5f * v[q] * (1.0f + erff(v[q] * 0.70710678118654752f));
            }
            const int row0 = bm + warpM + mt * 16 + g;
            const int row1 = row0 + 8;
            if (EPI == 1 || EPI == 3) {
                const float2 r0 = *(const float2*)(res + (size_t)row0 * N + col);
                const float2 r1 = *(const float2*)(res + (size_t)row1 * N + col);
                v[0] += r0.x; v[1] += r0.y; v[2] += r1.x; v[3] += r1.y;
            }
            if (OF16) {
                *(uint32_t*)(Cs + (size_t)row0 * N + col) = pack2_hi(v[0], v[1]);
                *(uint32_t*)(Cs + (size_t)row1 * N + col) = pack2_hi(v[2], v[3]);
            } else {
                *(float2*)(C + (size_t)row0 * N + col) = make_float2(v[0], v[1]);
                *(float2*)(C + (size_t)row1 * N + col) = make_float2(v[2], v[3]);
            }
        }
    }
}

// ---------------------------------------------------------------------------
// Flash attention on tensor cores (fp16, Q/P 2-pass split internally). Causal.
// One CTA = one (b,h) x 128 query rows. Output dense fp16.
// ---------------------------------------------------------------------------
#define ATT_SMEM 65536

__global__ void __launch_bounds__(256, 2) attn_mma(const float* __restrict__ qkv,
                                                   uint16_t* __restrict__ outs)
{
    extern __shared__ __align__(1024) uint8_t asmem[];
    const uint32_t SU = smem_to_u32(asmem);
    const uint32_t QU = SU;
    const uint32_t KU = SU + 32768;
    const uint32_t VU = SU + 49152;

    const int bh = blockIdx.x;          // 0..255
    const int qb = blockIdx.y;          // 0..3
    const int b  = bh >> 4;
    const int h  = bh & 15;

    const int tid  = threadIdx.x;
    const int wid  = tid >> 5;
    const int lane = tid & 31;
    const int g    = lane >> 2;
    const int tig  = lane & 3;

    const int aRow = ((lane >> 3) & 1) * 8 + (lane & 7);
    const int aCol = (lane >> 4) * 16;
    const int bRow = (lane >> 4) * 8 + (lane & 7);
    const int bCol = ((lane >> 3) & 1) * 16;

    const float* base = qkv + (size_t)(b * SEQ) * (3 * DM) + h * HD;

    // ---- load Q block (scaled by 1/8), split hi+lo into 2 d-planes ----
    #pragma unroll
    for (int i = 0; i < 8; i++) {
        const int idx = tid + i * 256;
        const int row = idx >> 4;
        const int d0  = (idx & 15) * 4;
        float4 v = *(const float4*)(base + (size_t)(qb * 128 + row) * (3 * DM) + d0);
        v.x *= 0.125f; v.y *= 0.125f; v.z *= 0.125f; v.w *= 0.125f;
        uint2 hi, lo;
        split4_pack(v, hi, lo);
        const uint32_t pl = (d0 >> 5) * 16384;
        const uint32_t c2 = (d0 & 31) * 2;
        *(uint2*)(asmem + (pl + SMEM_SWIZZLE_128B((uint32_t)(row * 128 + c2))))      = hi;
        *(uint2*)(asmem + (pl + SMEM_SWIZZLE_128B((uint32_t)(row * 128 + 64 + c2)))) = lo;
    }

    float m[2]  = {-1e30f, -1e30f};
    float l[2]  = {0.0f, 0.0f};
    float O[8][4];
    #pragma unroll
    for (int nt = 0; nt < 8; nt++)
        #pragma unroll
        for (int q = 0; q < 4; q++) O[nt][q] = 0.0f;

    const int kbmax = qb * 2 + 1;
    const int qrow0 = qb * 128 + wid * 16 + g;
    for (int kb = 0; kb <= kbmax; kb++) {
        __syncthreads();
        // ---- load K (hi only) and V^T (hi only) ----
        #pragma unroll
        for (int i = 0; i < 4; i++) {
            const int idx = tid + i * 256;
            const int key = idx >> 4;
            const int d0  = (idx & 15) * 4;
            const size_t grow = (size_t)(kb * 64 + key) * (3 * DM);
            // K hi
            {
                float4 v = *(const float4*)(base + DM + grow + d0);
                __half2 h0 = __halves2half2(__float2half_rn(v.x), __float2half_rn(v.y));
                __half2 h1 = __halves2half2(__float2half_rn(v.z), __float2half_rn(v.w));
                uint2 hi; hi.x = *(uint32_t*)&h0; hi.y = *(uint32_t*)&h1;
                const uint32_t pl = 32768 + (d0 >> 5) * 8192;
                const uint32_t c2 = (d0 & 31) * 2;
                *(uint2*)(asmem + (pl + SMEM_SWIZZLE_128B((uint32_t)(key * 128 + c2)))) = hi;
            }
            // V transposed hi: dest row = d, col = key
            {
                float4 v = *(const float4*)(base + 2 * DM + grow + d0);
                const uint32_t pl = 49152 + (key >> 5) * 8192;
                const uint32_t kc = (key & 31) * 2;
                const float vv[4] = {v.x, v.y, v.z, v.w};
                #pragma unroll
                for (int j = 0; j < 4; j++) {
                    const int d = d0 + j;
                    const uint32_t oh = pl + SMEM_SWIZZLE_128B((uint32_t)(d * 128 + kc));
                    *(uint16_t*)(asmem + oh) = h16(vv[j]);
                }
            }
        }
        __syncthreads();

        // ---- S = Q K^T (2-pass) ----
        float sacc[8][4];
        #pragma unroll
        for (int nt = 0; nt < 8; nt++)
            #pragma unroll
            for (int q = 0; q < 4; q++) sacc[nt][q] = 0.0f;

        #pragma unroll
        for (int s = 0; s < 4; s++) {
            const uint32_t qpl = QU + (s >> 1) * 16384;
            const int kbH = (s & 1) * 32;
            const int kbL = 64 + (s & 1) * 32;
            const int ra = wid * 16 + aRow;
            uint32_t ahi[4], alo[4];
            ldmatrix_x4(ahi[0], ahi[1], ahi[2], ahi[3],
                qpl + SMEM_SWIZZLE_128B((uint32_t)(ra * 128 + kbH + aCol)));
            ldmatrix_x4(alo[0], alo[1], alo[2], alo[3],
                qpl + SMEM_SWIZZLE_128B((uint32_t)(ra * 128 + kbL + aCol)));

            const uint32_t kpl = KU + (s >> 1) * 8192;
            #pragma unroll
            for (int p = 0; p < 4; p++) {
                const int r = p * 16 + bRow;
                uint32_t bhi[4];
                ldmatrix_x4(bhi[0], bhi[1], bhi[2], bhi[3],
                    kpl + SMEM_SWIZZLE_128B((uint32_t)(r * 128 + kbH + bCol)));
                #pragma unroll
                for (int u = 0; u < 2; u++) {
                    const int nt = p * 2 + u;
                    mma_f16(sacc[nt], ahi, &bhi[u * 2]);
                    mma_f16(sacc[nt], alo, &bhi[u * 2]);
                }
            }
        }

        // ---- causal mask ----
        if (kb >= qb * 2) {
            #pragma unroll
            for (int nt = 0; nt < 8; nt++) {
                const int col = kb * 64 + nt * 8 + tig * 2;
                if (col     > qrow0)     sacc[nt][0] = -10000.0f;
                if (col + 1 > qrow0)     sacc[nt][1] = -10000.0f;
                if (col     > qrow0 + 8) sacc[nt][2] = -10000.0f;
                if (col + 1 > qrow0 + 8) sacc[nt][3] = -10000.0f;
            }
        }

        // ---- online softmax (2 rows per thread) ----
        #pragma unroll
        for (int rh = 0; rh < 2; rh++) {
            const int q0 = rh * 2;
            float rm = -1e30f;
            #pragma unroll
            for (int nt = 0; nt < 8; nt++)
                rm = fmaxf(rm, fmaxf(sacc[nt][q0], sacc[nt][q0 + 1]));
            rm = fmaxf(rm, __shfl_xor_sync(0xffffffffu, rm, 1));
            rm = fmaxf(rm, __shfl_xor_sync(0xffffffffu, rm, 2));
            const float mn = fmaxf(m[rh], rm);
            const float alpha = __expf(m[rh] - mn);
            float rs = 0.0f;
            #pragma unroll
            for (int nt = 0; nt < 8; nt++) {
                sacc[nt][q0]     = __expf(sacc[nt][q0] - mn);
                sacc[nt][q0 + 1] = __expf(sacc[nt][q0 + 1] - mn);
                rs += sacc[nt][q0] + sacc[nt][q0 + 1];
            }
            rs += __shfl_xor_sync(0xffffffffu, rs, 1);
            rs += __shfl_xor_sync(0xffffffffu, rs, 2);
            l[rh] = l[rh] * alpha + rs;
            m[rh] = mn;
            #pragma unroll
            for (int nt = 0; nt < 8; nt++) {
                O[nt][q0]     *= alpha;
                O[nt][q0 + 1] *= alpha;
            }
        }

        // ---- O += P V (P hi+lo, V hi) ----
        #pragma unroll
        for (int s = 0; s < 4; s++) {
            uint32_t phi[4], plo[4];
            phi[0] = pack2_hi(sacc[2*s][0],   sacc[2*s][1]);
            phi[1] = pack2_hi(sacc[2*s][2],   sacc[2*s][3]);
            phi[2] = pack2_hi(sacc[2*s+1][0], sacc[2*s+1][1]);
            phi[3] = pack2_hi(sacc[2*s+1][2], sacc[2*s+1][3]);
            plo[0] = pack2_lo(sacc[2*s][0],   sacc[2*s][1]);
            plo[1] = pack2_lo(sacc[2*s][2],   sacc[2*s][3]);
            plo[2] = pack2_lo(sacc[2*s+1][0], sacc[2*s+1][1]);
            plo[3] = pack2_lo(sacc[2*s+1][2], sacc[2*s+1][3]);

            const uint32_t vpl = VU + (s >> 1) * 8192;
            const int kbH = (s & 1) * 32;
            #pragma unroll
            for (int p = 0; p < 4; p++) {
                const int r = p * 16 + bRow;
                uint32_t vhi[4];
                ldmatrix_x4(vhi[0], vhi[1], vhi[2], vhi[3],
                    vpl + SMEM_SWIZZLE_128B((uint32_t)(r * 128 + kbH + bCol)));
                #pragma unroll
                for (int u = 0; u < 2; u++) {
                    const int nt = p * 2 + u;
                    mma_f16(O[nt], phi, &vhi[u * 2]);
                    mma_f16(O[nt], plo, &vhi[u * 2]);
                }
            }
        }
    }

    // ---- epilogue: normalize, write dense fp16 attention output ----
    const float inv0 = 1.0f / l[0];
    const float inv1 = 1.0f / l[1];
    const size_t grow0 = (size_t)(b * SEQ + qb * 128 + wid * 16 + g);
    #pragma unroll
    for (int nt = 0; nt < 8; nt++) {
        const int col = h * HD + nt * 8 + tig * 2;
        const float v0 = O[nt][0] * inv0, v1 = O[nt][1] * inv0;
        const float v2 = O[nt][2] * inv1, v3 = O[nt][3] * inv1;
        *(uint32_t*)(outs + grow0 * DM + col)       = pack2_hi(v0, v1);
        *(uint32_t*)(outs + (grow0 + 8) * DM + col) = pack2_hi(v2, v3);
    }
}

// ---------------------------------------------------------------------------
extern "C" void kernel_launch(void* const* d_in, const int* in_sizes, int n_in,
                              void* d_out, int out_size)
{
    const float* x      = (const float*)d_in[0];
    const float* w_qkv  = (const float*)d_in[1];
    const float* w_proj = (const float*)d_in[2];
    const float* w_ff1  = (const float*)d_in[3];
    const float* b_ff1  = (const float*)d_in[4];
    const float* w_ff2  = (const float*)d_in[5];
    const float* b_ff2  = (const float*)d_in[6];
    const float* ln1_g  = (const float*)d_in[7];
    const float* ln1_b  = (const float*)d_in[8];
    const float* ln2_g  = (const float*)d_in[9];
    const float* ln2_b  = (const float*)d_in[10];
    float* out = (float*)d_out;

    uint16_t *p_lns, *p_atts, *p_ffs, *p_wqkv, *p_wprj, *p_wff1, *p_wff2;
    float *p_qkv, *p_x1;
    cudaGetSymbolAddress((void**)&p_lns,  g_lns);
    cudaGetSymbolAddress((void**)&p_qkv,  g_qkv);
    cudaGetSymbolAddress((void**)&p_atts, g_atts);
    cudaGetSymbolAddress((void**)&p_x1,   g_x1);
    cudaGetSymbolAddress((void**)&p_ffs,  g_ffs);
    cudaGetSymbolAddress((void**)&p_wqkv, g_wqkv);
    cudaGetSymbolAddress((void**)&p_wprj, g_wprj);
    cudaGetSymbolAddress((void**)&p_wff1, g_wff1);
    cudaGetSymbolAddress((void**)&p_wff2, g_wff2);

    cudaFuncSetAttribute(attn_mma,
                         cudaFuncAttributeMaxDynamicSharedMemorySize, ATT_SMEM);
    cudaFuncSetAttribute(gemm_cp<0, false>,
                         cudaFuncAttributeMaxDynamicSharedMemorySize, GEMM_SMEM);
    cudaFuncSetAttribute(gemm_cp<1, false>,
                         cudaFuncAttributeMaxDynamicSharedMemorySize, GEMM_SMEM);
    cudaFuncSetAttribute(gemm_cp<2, true>,
                         cudaFuncAttributeMaxDynamicSharedMemorySize, GEMM_SMEM);
    cudaFuncSetAttribute(gemm_cp<3, false>,
                         cudaFuncAttributeMaxDynamicSharedMemorySize, GEMM_SMEM);

    // 0. convert weights to dense fp16
    split_kernel<<<3 * DM * DM / 1024, 256>>>(w_qkv,  p_wqkv, 3 * DM * DM);
    split_kernel<<<DM * DM / 1024, 256>>>(w_proj, p_wprj, DM * DM);
    split_kernel<<<DFF * DM / 1024, 256>>>(w_ff1,  p_wff1, DFF * DM);
    split_kernel<<<DM * DFF / 1024, 256>>>(w_ff2,  p_wff2, DM * DFF);

    // 1. LN1 (fp16 output)
    ln_kernel<<<MTOK, 256>>>(x, ln1_g, ln1_b, p_lns);
    // 2. QKV projection (fp32 out)
    gemm_cp<0, false><<<dim3(3 * DM / 128, MTOK / 128), 256, GEMM_SMEM>>>(
        p_lns, p_wqkv, nullptr, nullptr, p_qkv, nullptr, MTOK, 3 * DM, DM);
    // 3. causal flash attention on tensor cores (fp16 output)
    attn_mma<<<dim3(BATCH * NHEADS, SEQ / 128), 256, ATT_SMEM>>>(p_qkv, p_atts);
    // 4. out projection + residual (fp32 out)
    gemm_cp<1, false><<<dim3(DM / 128, MTOK / 128), 256, GEMM_SMEM>>>(
        p_atts, p_wprj, nullptr, x, p_x1, nullptr, MTOK, DM, DM);
    // 5. LN2 (fp16 output)
    ln_kernel<<<MTOK, 256>>>(p_x1, ln2_g, ln2_b, p_lns);
    // 6. FF1 + bias + exact GELU (fp16 output)
    gemm_cp<2, true><<<dim3(DFF / 128, MTOK / 128), 256, GEMM_SMEM>>>(
        p_lns, p_wff1, b_ff1, nullptr, nullptr, p_ffs, MTOK, DFF, DM);
    // 7. FF2 + bias + residual -> out (fp32)
    gemm_cp<3, false><<<dim3(DM / 128, MTOK / 128), 256, GEMM_SMEM>>>(
        p_ffs, p_wff2, b_ff2, p_x1, out, nullptr, MTOK, DM, DFF);
}